// round 4
// baseline (speedup 1.0000x reference)
#include <cuda_runtime.h>

#define BT 2048
#define NF 128
#define CC 256
#define DD 128

// Precomputed fused weight Wc = Wg @ Wv and bias bc = Wg @ bv + bg
__device__ float g_Wc[CC * CC];
__device__ float g_bc[CC];

__global__ void prep_kernel(const float* __restrict__ Wg, const float* __restrict__ Wv,
                            const float* __restrict__ bv, const float* __restrict__ bg)
{
    __shared__ float sWg[CC];
    __shared__ float sred[256];
    const int i = blockIdx.x;
    const int j = threadIdx.x;
    const float wg = Wg[i * CC + j];
    sWg[j] = wg;
    __syncthreads();
    float acc = 0.f;
#pragma unroll 8
    for (int k = 0; k < CC; ++k) acc = fmaf(sWg[k], Wv[k * CC + j], acc);
    g_Wc[i * CC + j] = acc;
    sred[j] = wg * bv[j];
    __syncthreads();
    for (int s = 128; s > 0; s >>= 1) {
        if (j < s) sred[j] += sred[j + s];
        __syncthreads();
    }
    if (j == 0) g_bc[i] = sred[0] + bg[i];
}

// Shared memory layout (floats)
constexpr int OFF_A   = 0;      // sQ [128][132], later attn [128][132]
constexpr int OFF_AX  = 16896;  // sKt [128][132] (phases 1-2), then ax [128][260]
constexpr int OFF_BT  = 50176;  // sBt staging [16][260]
constexpr int OFF_SA  = 54336;  // sA  staging [128][16]
constexpr int SMEM_FLOATS = 56384;   // 225536 bytes

__global__ void __launch_bounds__(256, 1)
fused_kernel(const float* __restrict__ x, const float* __restrict__ ee,
             const float* __restrict__ adj, const float* __restrict__ alpha_p,
             const float* __restrict__ Wq, const float* __restrict__ bq,
             const float* __restrict__ Wk, const float* __restrict__ bk,
             const float* __restrict__ gamma, const float* __restrict__ beta,
             float* __restrict__ out)
{
    extern __shared__ float sm[];
    float* sQ  = sm + OFF_A;    // stride 132 (also attn later)
    float* sKt = sm + OFF_AX;   // stride 132 (K transposed: [d][m])
    float* sAX = sm + OFF_AX;   // stride 260 (attn @ x, phases 3-4)
    float* sBt = sm + OFF_BT;   // stride 260
    float* sA  = sm + OFF_SA;   // stride 16

    const int tid = threadIdx.x;
    const int tm = tid >> 4;          // 0..15 (row group)
    const int tn = tid & 15;          // 0..15 (col group)
    const int rm = tm << 3;           // first of 8 rows owned by this thread
    const int b = blockIdx.x;
    const float* xb = x + (size_t)b * (NF * CC);

    float acc[8][16];

    // ================= Phase 1: [Q | K] = (x + ee) @ [Wq; Wk]^T + bias ============
#pragma unroll
    for (int i = 0; i < 8; i++)
#pragma unroll
        for (int j = 0; j < 16; j++) acc[i][j] = 0.f;

    for (int kt = 0; kt < CC; kt += 16) {
        { // stage xe tile: sA[r][kk] = x[b][r][kt+kk] + ee[r][kt+kk]
            const int r = tid >> 1;
            const int h = (tid & 1) << 3;
            const float* px = xb + r * CC + kt + h;
            const float* pe = ee + r * CC + kt + h;
            float4 v0 = *(const float4*)px;
            float4 v1 = *(const float4*)(px + 4);
            float4 e0 = *(const float4*)pe;
            float4 e1 = *(const float4*)(pe + 4);
            float* d = sA + r * 16 + h;
            d[0] = v0.x + e0.x; d[1] = v0.y + e0.y; d[2] = v0.z + e0.z; d[3] = v0.w + e0.w;
            d[4] = v1.x + e1.x; d[5] = v1.y + e1.y; d[6] = v1.z + e1.z; d[7] = v1.w + e1.w;
        }
        { // stage weight tile transposed: sBt[kk][n] = W[n][kt+kk], n = tid
            const float* wp = (tid < DD) ? (Wq + tid * CC + kt) : (Wk + (tid - DD) * CC + kt);
            float4 w0 = *(const float4*)wp;
            float4 w1 = *(const float4*)(wp + 4);
            float4 w2 = *(const float4*)(wp + 8);
            float4 w3 = *(const float4*)(wp + 12);
            float wv[16] = {w0.x, w0.y, w0.z, w0.w, w1.x, w1.y, w1.z, w1.w,
                            w2.x, w2.y, w2.z, w2.w, w3.x, w3.y, w3.z, w3.w};
#pragma unroll
            for (int kk = 0; kk < 16; kk++) sBt[kk * 260 + tid] = wv[kk];
        }
        __syncthreads();
#pragma unroll 4
        for (int kk = 0; kk < 16; kk++) {
            float a[8];
#pragma unroll
            for (int i = 0; i < 8; i++) a[i] = sA[(rm + i) * 16 + kk];
            float4 bb[4];
#pragma unroll
            for (int q = 0; q < 4; q++) bb[q] = *(const float4*)&sBt[kk * 260 + tn * 4 + q * 64];
#pragma unroll
            for (int i = 0; i < 8; i++) {
#pragma unroll
                for (int q = 0; q < 4; q++) {
                    acc[i][q * 4 + 0] = fmaf(a[i], bb[q].x, acc[i][q * 4 + 0]);
                    acc[i][q * 4 + 1] = fmaf(a[i], bb[q].y, acc[i][q * 4 + 1]);
                    acc[i][q * 4 + 2] = fmaf(a[i], bb[q].z, acc[i][q * 4 + 2]);
                    acc[i][q * 4 + 3] = fmaf(a[i], bb[q].w, acc[i][q * 4 + 3]);
                }
            }
        }
        __syncthreads();
    }
    // epilogue: Q rows -> sQ ; K rows transposed -> sKt[d][m]
#pragma unroll
    for (int q = 0; q < 4; q++) {
        const int n0 = tn * 4 + q * 64;
        if (q < 2) {
            float4 bias = *(const float4*)&bq[n0];
#pragma unroll
            for (int i = 0; i < 8; i++) {
                float4 v;
                v.x = acc[i][q * 4 + 0] + bias.x;
                v.y = acc[i][q * 4 + 1] + bias.y;
                v.z = acc[i][q * 4 + 2] + bias.z;
                v.w = acc[i][q * 4 + 3] + bias.w;
                *(float4*)&sQ[(rm + i) * 132 + n0] = v;
            }
        } else {
            const int nk = n0 - 128;
            float4 bias = *(const float4*)&bk[nk];
#pragma unroll
            for (int i = 0; i < 8; i++) {
                sKt[(nk + 0) * 132 + rm + i] = acc[i][q * 4 + 0] + bias.x;
                sKt[(nk + 1) * 132 + rm + i] = acc[i][q * 4 + 1] + bias.y;
                sKt[(nk + 2) * 132 + rm + i] = acc[i][q * 4 + 2] + bias.z;
                sKt[(nk + 3) * 132 + rm + i] = acc[i][q * 4 + 3] + bias.w;
            }
        }
    }
    __syncthreads();

    // ================= Phase 2: scores = Q K^T / sqrt(128) + fa*relu(adj); softmax =====
    float sc[8][8];
#pragma unroll
    for (int i = 0; i < 8; i++)
#pragma unroll
        for (int j = 0; j < 8; j++) sc[i][j] = 0.f;

#pragma unroll 4
    for (int d = 0; d < DD; d++) {
        float a[8];
#pragma unroll
        for (int i = 0; i < 8; i++) a[i] = sQ[(rm + i) * 132 + d];
        float4 b0 = *(const float4*)&sKt[d * 132 + tn * 4];
        float4 b1 = *(const float4*)&sKt[d * 132 + tn * 4 + 64];
#pragma unroll
        for (int i = 0; i < 8; i++) {
            sc[i][0] = fmaf(a[i], b0.x, sc[i][0]);
            sc[i][1] = fmaf(a[i], b0.y, sc[i][1]);
            sc[i][2] = fmaf(a[i], b0.z, sc[i][2]);
            sc[i][3] = fmaf(a[i], b0.w, sc[i][3]);
            sc[i][4] = fmaf(a[i], b1.x, sc[i][4]);
            sc[i][5] = fmaf(a[i], b1.y, sc[i][5]);
            sc[i][6] = fmaf(a[i], b1.z, sc[i][6]);
            sc[i][7] = fmaf(a[i], b1.w, sc[i][7]);
        }
    }
    const float fa = __ldg(alpha_p);
    const float invscale = 0.08838834764831845f;  // 1/sqrt(128)
#pragma unroll
    for (int i = 0; i < 8; i++) {
        const int gi = rm + i;
        float4 a0 = __ldg((const float4*)&adj[gi * DD + tn * 4]);
        float4 a1 = __ldg((const float4*)&adj[gi * DD + tn * 4 + 64]);
        sc[i][0] = sc[i][0] * invscale + fa * fmaxf(a0.x, 0.f);
        sc[i][1] = sc[i][1] * invscale + fa * fmaxf(a0.y, 0.f);
        sc[i][2] = sc[i][2] * invscale + fa * fmaxf(a0.z, 0.f);
        sc[i][3] = sc[i][3] * invscale + fa * fmaxf(a0.w, 0.f);
        sc[i][4] = sc[i][4] * invscale + fa * fmaxf(a1.x, 0.f);
        sc[i][5] = sc[i][5] * invscale + fa * fmaxf(a1.y, 0.f);
        sc[i][6] = sc[i][6] * invscale + fa * fmaxf(a1.z, 0.f);
        sc[i][7] = sc[i][7] * invscale + fa * fmaxf(a1.w, 0.f);
        float mx = sc[i][0];
#pragma unroll
        for (int j = 1; j < 8; j++) mx = fmaxf(mx, sc[i][j]);
#pragma unroll
        for (int off = 8; off; off >>= 1) mx = fmaxf(mx, __shfl_xor_sync(0xffffffffu, mx, off));
        float s = 0.f;
#pragma unroll
        for (int j = 0; j < 8; j++) { sc[i][j] = __expf(sc[i][j] - mx); s += sc[i][j]; }
#pragma unroll
        for (int off = 8; off; off >>= 1) s += __shfl_xor_sync(0xffffffffu, s, off);
        const float inv = 1.f / s;
#pragma unroll
        for (int j = 0; j < 8; j++) sc[i][j] *= inv;
    }
    __syncthreads();   // everyone done reading sQ/sKt
#pragma unroll
    for (int i = 0; i < 8; i++) {  // attn overwrites sQ region
        *(float4*)&sQ[(rm + i) * 132 + tn * 4]      = make_float4(sc[i][0], sc[i][1], sc[i][2], sc[i][3]);
        *(float4*)&sQ[(rm + i) * 132 + tn * 4 + 64] = make_float4(sc[i][4], sc[i][5], sc[i][6], sc[i][7]);
    }
    __syncthreads();

    // ================= Phase 3: ax = attn @ x[b]  (128x256, K=128) ==================
#pragma unroll
    for (int i = 0; i < 8; i++)
#pragma unroll
        for (int j = 0; j < 16; j++) acc[i][j] = 0.f;

    for (int kt = 0; kt < DD; kt += 16) {
        { // stage x rows: sBt[kk][n] = x[b][kt+kk][n]
            const int kk = tid >> 4;
            const int n0 = (tid & 15) << 4;
            const float* px = xb + (kt + kk) * CC + n0;
            float4 v0 = *(const float4*)px;
            float4 v1 = *(const float4*)(px + 4);
            float4 v2 = *(const float4*)(px + 8);
            float4 v3 = *(const float4*)(px + 12);
            float* d = &sBt[kk * 260 + n0];
            *(float4*)(d)      = v0;
            *(float4*)(d + 4)  = v1;
            *(float4*)(d + 8)  = v2;
            *(float4*)(d + 12) = v3;
        }
        __syncthreads();
#pragma unroll 4
        for (int kk = 0; kk < 16; kk++) {
            float a[8];
#pragma unroll
            for (int i = 0; i < 8; i++) a[i] = sQ[(rm + i) * 132 + kt + kk];  // attn
            float4 bb[4];
#pragma unroll
            for (int q = 0; q < 4; q++) bb[q] = *(const float4*)&sBt[kk * 260 + tn * 4 + q * 64];
#pragma unroll
            for (int i = 0; i < 8; i++) {
#pragma unroll
                for (int q = 0; q < 4; q++) {
                    acc[i][q * 4 + 0] = fmaf(a[i], bb[q].x, acc[i][q * 4 + 0]);
                    acc[i][q * 4 + 1] = fmaf(a[i], bb[q].y, acc[i][q * 4 + 1]);
                    acc[i][q * 4 + 2] = fmaf(a[i], bb[q].z, acc[i][q * 4 + 2]);
                    acc[i][q * 4 + 3] = fmaf(a[i], bb[q].w, acc[i][q * 4 + 3]);
                }
            }
        }
        __syncthreads();
    }
#pragma unroll
    for (int q = 0; q < 4; q++) {
        const int n0 = tn * 4 + q * 64;
#pragma unroll
        for (int i = 0; i < 8; i++)
            *(float4*)&sAX[(rm + i) * 260 + n0] =
                make_float4(acc[i][q * 4 + 0], acc[i][q * 4 + 1], acc[i][q * 4 + 2], acc[i][q * 4 + 3]);
    }
    __syncthreads();

    // ================= Phase 4: out = LN( relu(ax @ Wc^T + bc) + x ) ================
#pragma unroll
    for (int i = 0; i < 8; i++)
#pragma unroll
        for (int j = 0; j < 16; j++) acc[i][j] = 0.f;

    for (int kt = 0; kt < CC; kt += 16) {
        { // stage Wc rows transposed: sBt[kk][n] = Wc[n][kt+kk]
            const float* wp = g_Wc + tid * CC + kt;
            float4 w0 = *(const float4*)wp;
            float4 w1 = *(const float4*)(wp + 4);
            float4 w2 = *(const float4*)(wp + 8);
            float4 w3 = *(const float4*)(wp + 12);
            float wv[16] = {w0.x, w0.y, w0.z, w0.w, w1.x, w1.y, w1.z, w1.w,
                            w2.x, w2.y, w2.z, w2.w, w3.x, w3.y, w3.z, w3.w};
#pragma unroll
            for (int kk = 0; kk < 16; kk++) sBt[kk * 260 + tid] = wv[kk];
        }
        __syncthreads();
#pragma unroll 4
        for (int kk = 0; kk < 16; kk++) {
            float a[8];
#pragma unroll
            for (int i = 0; i < 8; i++) a[i] = sAX[(rm + i) * 260 + kt + kk];
            float4 bb[4];
#pragma unroll
            for (int q = 0; q < 4; q++) bb[q] = *(const float4*)&sBt[kk * 260 + tn * 4 + q * 64];
#pragma unroll
            for (int i = 0; i < 8; i++) {
#pragma unroll
                for (int q = 0; q < 4; q++) {
                    acc[i][q * 4 + 0] = fmaf(a[i], bb[q].x, acc[i][q * 4 + 0]);
                    acc[i][q * 4 + 1] = fmaf(a[i], bb[q].y, acc[i][q * 4 + 1]);
                    acc[i][q * 4 + 2] = fmaf(a[i], bb[q].z, acc[i][q * 4 + 2]);
                    acc[i][q * 4 + 3] = fmaf(a[i], bb[q].w, acc[i][q * 4 + 3]);
                }
            }
        }
        __syncthreads();
    }
    // epilogue: bias, relu, residual, LayerNorm
    float hs[8], s2[8];
#pragma unroll
    for (int i = 0; i < 8; i++) { hs[i] = 0.f; s2[i] = 0.f; }
#pragma unroll
    for (int q = 0; q < 4; q++) {
        const int n0 = tn * 4 + q * 64;
        float4 bc4 = *(const float4*)&g_bc[n0];
#pragma unroll
        for (int i = 0; i < 8; i++) {
            float4 xv = __ldg((const float4*)&xb[(rm + i) * CC + n0]);
            float h0 = fmaxf(acc[i][q * 4 + 0] + bc4.x, 0.f) + xv.x;
            float h1 = fmaxf(acc[i][q * 4 + 1] + bc4.y, 0.f) + xv.y;
            float h2 = fmaxf(acc[i][q * 4 + 2] + bc4.z, 0.f) + xv.z;
            float h3 = fmaxf(acc[i][q * 4 + 3] + bc4.w, 0.f) + xv.w;
            acc[i][q * 4 + 0] = h0; acc[i][q * 4 + 1] = h1;
            acc[i][q * 4 + 2] = h2; acc[i][q * 4 + 3] = h3;
            hs[i] += (h0 + h1) + (h2 + h3);
            s2[i] += (h0 * h0 + h1 * h1) + (h2 * h2 + h3 * h3);
        }
    }
#pragma unroll
    for (int i = 0; i < 8; i++) {
        float S = hs[i], Q2 = s2[i];
#pragma unroll
        for (int off = 8; off; off >>= 1) {
            S  += __shfl_xor_sync(0xffffffffu, S, off);
            Q2 += __shfl_xor_sync(0xffffffffu, Q2, off);
        }
        const float mean = S * (1.f / 256.f);
        const float var = Q2 * (1.f / 256.f) - mean * mean;
        hs[i] = mean;
        s2[i] = rsqrtf(var + 1e-5f);
    }
    float* ob = out + (size_t)b * (NF * CC);
#pragma unroll
    for (int q = 0; q < 4; q++) {
        const int n0 = tn * 4 + q * 64;
        float4 g4 = __ldg((const float4*)&gamma[n0]);
        float4 b4 = __ldg((const float4*)&beta[n0]);
#pragma unroll
        for (int i = 0; i < 8; i++) {
            const float m = hs[i], r = s2[i];
            float4 o;
            o.x = (acc[i][q * 4 + 0] - m) * r * g4.x + b4.x;
            o.y = (acc[i][q * 4 + 1] - m) * r * g4.y + b4.y;
            o.z = (acc[i][q * 4 + 2] - m) * r * g4.z + b4.z;
            o.w = (acc[i][q * 4 + 3] - m) * r * g4.w + b4.w;
            *(float4*)&ob[(rm + i) * CC + n0] = o;
        }
    }
}

extern "C" void kernel_launch(void* const* d_in, const int* in_sizes, int n_in,
                              void* d_out, int out_size)
{
    (void)in_sizes; (void)n_in; (void)out_size;
    const float* x     = (const float*)d_in[0];
    const float* ee    = (const float*)d_in[1];
    const float* adj   = (const float*)d_in[2];
    const float* alpha = (const float*)d_in[3];
    const float* Wq    = (const float*)d_in[4];
    const float* bq    = (const float*)d_in[5];
    const float* Wk    = (const float*)d_in[6];
    const float* bk    = (const float*)d_in[7];
    const float* Wv    = (const float*)d_in[8];
    const float* bv    = (const float*)d_in[9];
    const float* Wg    = (const float*)d_in[10];
    const float* bg    = (const float*)d_in[11];
    const float* gamma = (const float*)d_in[12];
    const float* beta  = (const float*)d_in[13];
    float* out = (float*)d_out;

    cudaFuncSetAttribute(fused_kernel, cudaFuncAttributeMaxDynamicSharedMemorySize,
                         SMEM_FLOATS * (int)sizeof(float));
    prep_kernel<<<CC, 256>>>(Wg, Wv, bv, bg);
    fused_kernel<<<BT, 256, SMEM_FLOATS * sizeof(float)>>>(
        x, ee, adj, alpha, Wq, bq, Wk, bk, gamma, beta, out);
}

// round 6
// speedup vs baseline: 2.2458x; 2.2458x over previous
#include <cuda_runtime.h>
#include <cstdint>

#define BT 2048
#define NF 128
#define CC 256

// Device-global precomputed weights (no allocations)
__device__ float g_Wct[CC * CC];    // Wc = Wg @ Wv (fp32, temp)
__device__ float g_WqkT[CC * CC];   // [k][n]: n<128 -> Wq[n][k], else Wk[n-128][k], tf32
__device__ float g_WctT[CC * CC];   // [k][n] = Wc[n][k], tf32
__device__ float g_bc[CC];          // Wg @ bv + bg

__device__ __forceinline__ float ftf32(float x) {
    uint32_t u;
    asm("cvt.rna.tf32.f32 %0, %1;" : "=r"(u) : "f"(x));
    return __uint_as_float(u);
}

__device__ __forceinline__ void mma8(float c[4], uint32_t a0, uint32_t a1, uint32_t a2,
                                     uint32_t a3, uint32_t b0, uint32_t b1) {
    asm volatile(
        "mma.sync.aligned.m16n8k8.row.col.f32.tf32.tf32.f32 "
        "{%0,%1,%2,%3},{%4,%5,%6,%7},{%8,%9},{%0,%1,%2,%3};"
        : "+f"(c[0]), "+f"(c[1]), "+f"(c[2]), "+f"(c[3])
        : "r"(a0), "r"(a1), "r"(a2), "r"(a3), "r"(b0), "r"(b1));
}

// One k8-step of a warp-tile GEMM. A row-major [m][k] stride As (As%32==4 -> conflict-free),
// B row-major [k][n] stride Bs (Bs%32==8 -> conflict-free). g=lane>>2, t=lane&3.
template <int NT>
__device__ __forceinline__ void mma_tile(float (&acc)[4][8][4], const float* A, int As,
                                         const float* B, int Bs, int g, int t) {
    uint32_t a[4][4];
#pragma unroll
    for (int mt = 0; mt < 4; mt++) {
        const float* ap = A + (mt * 16 + g) * As + t;
        a[mt][0] = __float_as_uint(ap[0]);
        a[mt][1] = __float_as_uint(ap[8 * As]);
        a[mt][2] = __float_as_uint(ap[4]);
        a[mt][3] = __float_as_uint(ap[8 * As + 4]);
    }
#pragma unroll
    for (int nt = 0; nt < NT; nt++) {
        const float* bp = B + t * Bs + nt * 8 + g;
        uint32_t b0 = __float_as_uint(bp[0]);
        uint32_t b1 = __float_as_uint(bp[4 * Bs]);
#pragma unroll
        for (int mt = 0; mt < 4; mt++)
            mma8(acc[mt][nt], a[mt][0], a[mt][1], a[mt][2], a[mt][3], b0, b1);
    }
}

// ---------------- prep 1: Wc = Wg @ Wv, bc = Wg @ bv + bg ----------------
__global__ void prep_wc(const float* __restrict__ Wg, const float* __restrict__ Wv,
                        const float* __restrict__ bv, const float* __restrict__ bg)
{
    __shared__ float sWg[CC];
    __shared__ float sred[CC];
    const int i = blockIdx.x;
    const int j = threadIdx.x;
    const float wg = Wg[i * CC + j];
    sWg[j] = wg;
    __syncthreads();
    float acc = 0.f;
#pragma unroll 8
    for (int k = 0; k < CC; ++k) acc = fmaf(sWg[k], Wv[k * CC + j], acc);
    g_Wct[i * CC + j] = acc;
    sred[j] = wg * bv[j];
    __syncthreads();
    for (int s = 128; s > 0; s >>= 1) {
        if (j < s) sred[j] += sred[j + s];
        __syncthreads();
    }
    if (j == 0) g_bc[i] = sred[0] + bg[i];
}

// ---------------- prep 2: transposed tf32 weights [k][n] ----------------
__global__ void prep_tr(const float* __restrict__ Wq, const float* __restrict__ Wk)
{
    __shared__ float tile[32][33];
    const int kb = blockIdx.x * 32, nb = blockIdx.y * 32, z = blockIdx.z;
    const int tx = threadIdx.x, ty = threadIdx.y;
    const int n = nb + ty, k = kb + tx;
    float v;
    if (z == 0) v = (n < 128) ? Wq[n * CC + k] : Wk[(n - 128) * CC + k];
    else        v = g_Wct[n * CC + k];
    tile[ty][tx] = v;
    __syncthreads();
    const float o = ftf32(tile[tx][ty]);   // src (n=nb+tx, k=kb+ty)
    if (z == 0) g_WqkT[(kb + ty) * CC + nb + tx] = o;
    else        g_WctT[(kb + ty) * CC + nb + tx] = o;
}

// ---------------- fused kernel ----------------
// SMEM floats: scr[1024] | BufA[34304] (xe[128][260] / Q[128][132]+Kt[128][136] / ax[128][260])
//            | Attn[128][132]=16896 | sB[16][264]=4224   -> 56448 fl = 225792 B
constexpr int OFF_SCR = 0;
constexpr int OFF_A   = 1024;
constexpr int OFF_KT  = OFF_A + 128 * 132;          // Kt after Q
constexpr int OFF_ATT = OFF_A + 34304;
constexpr int OFF_B   = OFF_ATT + 128 * 132;
constexpr int SMEM_FL = OFF_B + 16 * 264;           // 56448
constexpr int SMEM_BYTES = SMEM_FL * 4;             // 225792

__global__ void __launch_bounds__(256, 1)
fused_kernel(const float* __restrict__ x, const float* __restrict__ ee,
             const float* __restrict__ adj, const float* __restrict__ alpha_p,
             const float* __restrict__ bq, const float* __restrict__ bk,
             const float* __restrict__ gamma, const float* __restrict__ beta,
             float* __restrict__ out)
{
    extern __shared__ float sm[];
    float* scr = sm + OFF_SCR;
    float* sXE = sm + OFF_A;      // xe / ax, stride 260
    float* sQ  = sm + OFF_A;      // Q, stride 132
    float* sKT = sm + OFF_KT;     // K^T [k][n], stride 136
    float* sAT = sm + OFF_ATT;    // attn, stride 132
    float* sB  = sm + OFF_B;      // B chunk [16][264]

    const int tid = threadIdx.x;
    const int w = tid >> 5, lane = tid & 31;
    const int g = lane >> 2, t = lane & 3;
    const int mrow = (w >> 2) * 64;     // 0 | 64
    const int nq = w & 3;
    const int ncol = nq * 64;           // phases 1,3,4 (N=256)
    const int ncol2 = nq * 32;          // phase 2 (N=128)
    const int b = blockIdx.x;
    const float* xb = x + (size_t)b * (NF * CC);

    float acc[4][8][4];

    // ===== stage xe = tf32(x + ee), [128][260] =====
#pragma unroll 4
    for (int it = 0; it < 32; it++) {
        int f = it * 256 + tid;
        int r = f >> 6, k = (f & 63) << 2;
        float4 v = __ldg((const float4*)(xb + r * 256 + k));
        float4 e = __ldg((const float4*)(ee + r * 256 + k));
        float4 o;
        o.x = ftf32(v.x + e.x); o.y = ftf32(v.y + e.y);
        o.z = ftf32(v.z + e.z); o.w = ftf32(v.w + e.w);
        *(float4*)(sXE + r * 260 + k) = o;
    }

    // ===== Phase 1: [Q|K] = xe @ Wqk^T  (K=256, 16 chunks of 16) =====
#pragma unroll
    for (int mt = 0; mt < 4; mt++)
#pragma unroll
        for (int nt = 0; nt < 8; nt++)
#pragma unroll
            for (int e = 0; e < 4; e++) acc[mt][nt][e] = 0.f;

    for (int c = 0; c < 16; c++) {
        {   // stage sB[r][n] = WqkT[c*16+r][n] (already tf32)
            int r = tid >> 4, n0 = (tid & 15) << 4;
            const float* src = g_WqkT + (c * 16 + r) * 256 + n0;
            float* dst = sB + r * 264 + n0;
            *(float4*)(dst + 0)  = *(const float4*)(src + 0);
            *(float4*)(dst + 4)  = *(const float4*)(src + 4);
            *(float4*)(dst + 8)  = *(const float4*)(src + 8);
            *(float4*)(dst + 12) = *(const float4*)(src + 12);
        }
        __syncthreads();
#pragma unroll
        for (int s = 0; s < 2; s++)
            mma_tile<8>(acc, sXE + mrow * 260 + c * 16 + s * 8, 260,
                        sB + s * 8 * 264 + ncol, 264, g, t);
        __syncthreads();
    }
    // epilogue: Q rows (n<128) and K^T (n>=128), +bias, tf32
#pragma unroll
    for (int nt = 0; nt < 8; nt++) {
        const int n = ncol + nt * 8 + 2 * t;
#pragma unroll
        for (int mt = 0; mt < 4; mt++) {
            const int r0 = mrow + mt * 16 + g, r1 = r0 + 8;
            if (n < 128) {
                float b0 = __ldg(&bq[n]), b1 = __ldg(&bq[n + 1]);
                sQ[r0 * 132 + n]     = ftf32(acc[mt][nt][0] + b0);
                sQ[r0 * 132 + n + 1] = ftf32(acc[mt][nt][1] + b1);
                sQ[r1 * 132 + n]     = ftf32(acc[mt][nt][2] + b0);
                sQ[r1 * 132 + n + 1] = ftf32(acc[mt][nt][3] + b1);
            } else {
                const int nk = n - 128;
                float b0 = __ldg(&bk[nk]), b1 = __ldg(&bk[nk + 1]);
                sKT[nk * 136 + r0]       = ftf32(acc[mt][nt][0] + b0);
                sKT[(nk + 1) * 136 + r0] = ftf32(acc[mt][nt][1] + b1);
                sKT[nk * 136 + r1]       = ftf32(acc[mt][nt][2] + b0);
                sKT[(nk + 1) * 136 + r1] = ftf32(acc[mt][nt][3] + b1);
            }
        }
    }
    __syncthreads();

    // ===== Phase 2: scores = Q @ K^T  (K=128, N=128) =====
#pragma unroll
    for (int mt = 0; mt < 4; mt++)
#pragma unroll
        for (int nt = 0; nt < 4; nt++)
#pragma unroll
            for (int e = 0; e < 4; e++) acc[mt][nt][e] = 0.f;
#pragma unroll
    for (int ks = 0; ks < 16; ks++)
        mma_tile<4>(acc, sQ + mrow * 132 + ks * 8, 132,
                    sKT + ks * 8 * 136 + ncol2, 136, g, t);

    // ===== softmax(scores/sqrt(128) + fa*relu(adj)) -> attn =====
    {
        const float fa = __ldg(alpha_p);
        const float invs = 0.08838834764831845f;
        float rmax[4][2];
#pragma unroll
        for (int mt = 0; mt < 4; mt++)
#pragma unroll
            for (int h = 0; h < 2; h++) {
                const int r = mrow + mt * 16 + g + h * 8;
                float mx = -3.4e38f;
#pragma unroll
                for (int nt = 0; nt < 4; nt++)
#pragma unroll
                    for (int e = 0; e < 2; e++) {
                        const int col = ncol2 + nt * 8 + 2 * t + e;
                        float v = acc[mt][nt][h * 2 + e] * invs
                                + fa * fmaxf(__ldg(&adj[r * 128 + col]), 0.f);
                        acc[mt][nt][h * 2 + e] = v;
                        mx = fmaxf(mx, v);
                    }
                mx = fmaxf(mx, __shfl_xor_sync(0xffffffffu, mx, 1));
                mx = fmaxf(mx, __shfl_xor_sync(0xffffffffu, mx, 2));
                scr[r * 4 + nq] = mx;
            }
        __syncthreads();
#pragma unroll
        for (int mt = 0; mt < 4; mt++)
#pragma unroll
            for (int h = 0; h < 2; h++) {
                const int r = mrow + mt * 16 + g + h * 8;
                const float mx = fmaxf(fmaxf(scr[r * 4], scr[r * 4 + 1]),
                                       fmaxf(scr[r * 4 + 2], scr[r * 4 + 3]));
                rmax[mt][h] = mx;
                float s = 0.f;
#pragma unroll
                for (int nt = 0; nt < 4; nt++)
#pragma unroll
                    for (int e = 0; e < 2; e++) {
                        float p = __expf(acc[mt][nt][h * 2 + e] - mx);
                        acc[mt][nt][h * 2 + e] = p;
                        s += p;
                    }
                s += __shfl_xor_sync(0xffffffffu, s, 1);
                s += __shfl_xor_sync(0xffffffffu, s, 2);
                scr[512 + r * 4 + nq] = s;
            }
        __syncthreads();
#pragma unroll
        for (int mt = 0; mt < 4; mt++)
#pragma unroll
            for (int h = 0; h < 2; h++) {
                const int r = mrow + mt * 16 + g + h * 8;
                const float inv = 1.f / (scr[512 + r * 4] + scr[512 + r * 4 + 1]
                                       + scr[512 + r * 4 + 2] + scr[512 + r * 4 + 3]);
#pragma unroll
                for (int nt = 0; nt < 4; nt++)
#pragma unroll
                    for (int e = 0; e < 2; e++) {
                        const int col = ncol2 + nt * 8 + 2 * t + e;
                        sAT[r * 132 + col] = ftf32(acc[mt][nt][h * 2 + e] * inv);
                    }
                (void)rmax[mt][h];
            }
    }
    __syncthreads();

    // ===== Phase 3: ax = attn @ x  (K=128, 8 chunks of 16) =====
#pragma unroll
    for (int mt = 0; mt < 4; mt++)
#pragma unroll
        for (int nt = 0; nt < 8; nt++)
#pragma unroll
            for (int e = 0; e < 4; e++) acc[mt][nt][e] = 0.f;

    for (int c = 0; c < 8; c++) {
        {   // stage sB[r][n] = tf32(x[c*16+r][n])
            int r = tid >> 4, n0 = (tid & 15) << 4;
            const float* src = xb + (c * 16 + r) * 256 + n0;
            float* dst = sB + r * 264 + n0;
#pragma unroll
            for (int q = 0; q < 4; q++) {
                float4 v = __ldg((const float4*)(src + q * 4));
                float4 o;
                o.x = ftf32(v.x); o.y = ftf32(v.y); o.z = ftf32(v.z); o.w = ftf32(v.w);
                *(float4*)(dst + q * 4) = o;
            }
        }
        __syncthreads();
#pragma unroll
        for (int s = 0; s < 2; s++)
            mma_tile<8>(acc, sAT + mrow * 132 + c * 16 + s * 8, 132,
                        sB + s * 8 * 264 + ncol, 264, g, t);
        __syncthreads();
    }
    // epilogue: ax -> sXE [128][260] (tf32), overwrites Q/Kt (dead)
#pragma unroll
    for (int nt = 0; nt < 8; nt++) {
        const int n = ncol + nt * 8 + 2 * t;
#pragma unroll
        for (int mt = 0; mt < 4; mt++) {
            const int r0 = mrow + mt * 16 + g, r1 = r0 + 8;
            sXE[r0 * 260 + n]     = ftf32(acc[mt][nt][0]);
            sXE[r0 * 260 + n + 1] = ftf32(acc[mt][nt][1]);
            sXE[r1 * 260 + n]     = ftf32(acc[mt][nt][2]);
            sXE[r1 * 260 + n + 1] = ftf32(acc[mt][nt][3]);
        }
    }
    __syncthreads();

    // ===== Phase 4: z = ax @ Wc^T  (K=256, 16 chunks) =====
#pragma unroll
    for (int mt = 0; mt < 4; mt++)
#pragma unroll
        for (int nt = 0; nt < 8; nt++)
#pragma unroll
            for (int e = 0; e < 4; e++) acc[mt][nt][e] = 0.f;

    for (int c = 0; c < 16; c++) {
        {
            int r = tid >> 4, n0 = (tid & 15) << 4;
            const float* src = g_WctT + (c * 16 + r) * 256 + n0;
            float* dst = sB + r * 264 + n0;
            *(float4*)(dst + 0)  = *(const float4*)(src + 0);
            *(float4*)(dst + 4)  = *(const float4*)(src + 4);
            *(float4*)(dst + 8)  = *(const float4*)(src + 8);
            *(float4*)(dst + 12) = *(const float4*)(src + 12);
        }
        __syncthreads();
#pragma unroll
        for (int s = 0; s < 2; s++)
            mma_tile<8>(acc, sXE + mrow * 260 + c * 16 + s * 8, 260,
                        sB + s * 8 * 264 + ncol, 264, g, t);
        __syncthreads();
    }

    // ===== LN epilogue: h = relu(z + bc) + x; LayerNorm; store =====
#pragma unroll
    for (int mt = 0; mt < 4; mt++)
#pragma unroll
        for (int h = 0; h < 2; h++) {
            const int r = mrow + mt * 16 + g + h * 8;
            float s1 = 0.f, s2 = 0.f;
#pragma unroll
            for (int nt = 0; nt < 8; nt++)
#pragma unroll
                for (int e = 0; e < 2; e++) {
                    const int n = ncol + nt * 8 + 2 * t + e;
                    float hv = fmaxf(acc[mt][nt][h * 2 + e] + __ldg(&g_bc[n]), 0.f)
                             + __ldg(&xb[r * 256 + n]);
                    acc[mt][nt][h * 2 + e] = hv;
                    s1 += hv;
                    s2 += hv * hv;
                }
            s1 += __shfl_xor_sync(0xffffffffu, s1, 1);
            s1 += __shfl_xor_sync(0xffffffffu, s1, 2);
            s2 += __shfl_xor_sync(0xffffffffu, s2, 1);
            s2 += __shfl_xor_sync(0xffffffffu, s2, 2);
            scr[r * 4 + nq] = s1;
            scr[512 + r * 4 + nq] = s2;
        }
    __syncthreads();
    float* ob = out + (size_t)b * (NF * CC);
#pragma unroll
    for (int mt = 0; mt < 4; mt++)
#pragma unroll
        for (int h = 0; h < 2; h++) {
            const int r = mrow + mt * 16 + g + h * 8;
            const float S  = scr[r * 4] + scr[r * 4 + 1] + scr[r * 4 + 2] + scr[r * 4 + 3];
            const float Q2 = scr[512 + r * 4] + scr[512 + r * 4 + 1]
                           + scr[512 + r * 4 + 2] + scr[512 + r * 4 + 3];
            const float mean = S * (1.f / 256.f);
            const float rstd = rsqrtf(Q2 * (1.f / 256.f) - mean * mean + 1e-5f);
#pragma unroll
            for (int nt = 0; nt < 8; nt++) {
                const int n = ncol + nt * 8 + 2 * t;
                float2 o;
                o.x = (acc[mt][nt][h * 2 + 0] - mean) * rstd * __ldg(&gamma[n]) + __ldg(&beta[n]);
                o.y = (acc[mt][nt][h * 2 + 1] - mean) * rstd * __ldg(&gamma[n + 1]) + __ldg(&beta[n + 1]);
                *(float2*)(ob + r * 256 + n) = o;
            }
        }
}

extern "C" void kernel_launch(void* const* d_in, const int* in_sizes, int n_in,
                              void* d_out, int out_size)
{
    (void)in_sizes; (void)n_in; (void)out_size;
    const float* x     = (const float*)d_in[0];
    const float* ee    = (const float*)d_in[1];
    const float* adj   = (const float*)d_in[2];
    const float* alpha = (const float*)d_in[3];
    const float* Wq    = (const float*)d_in[4];
    const float* bq    = (const float*)d_in[5];
    const float* Wk    = (const float*)d_in[6];
    const float* bk    = (const float*)d_in[7];
    const float* Wv    = (const float*)d_in[8];
    const float* bv    = (const float*)d_in[9];
    const float* Wg    = (const float*)d_in[10];
    const float* bg    = (const float*)d_in[11];
    const float* gamma = (const float*)d_in[12];
    const float* beta  = (const float*)d_in[13];
    float* out = (float*)d_out;

    cudaFuncSetAttribute(fused_kernel, cudaFuncAttributeMaxDynamicSharedMemorySize, SMEM_BYTES);
    prep_wc<<<CC, 256>>>(Wg, Wv, bv, bg);
    prep_tr<<<dim3(8, 8, 2), dim3(32, 32)>>>(Wq, Wk);
    fused_kernel<<<BT, 256, SMEM_BYTES>>>(x, ee, adj, alpha, bq, bk, gamma, beta, out);
}

// round 8
// speedup vs baseline: 2.4957x; 1.1112x over previous
#include <cuda_runtime.h>
#include <cstdint>

#define BT 2048
#define NF 128
#define CC 256

// Device globals (no allocations)
__device__ float g_Wct[CC * CC];    // Wc = Wg @ Wv (fp32 temp)
__device__ float g_WqkP[CC * CC];   // fragment-packed B for phase 1 (tf32)
__device__ float g_WctP[CC * CC];   // fragment-packed B for phase 4 (tf32)
__device__ float g_bc[CC];          // Wg @ bv + bg

__device__ __forceinline__ float ftf32(float x) {
    uint32_t u;
    asm("cvt.rna.tf32.f32 %0, %1;" : "=r"(u) : "f"(x));
    return __uint_as_float(u);
}
__device__ __forceinline__ uint32_t smem_u32(const void* p) {
    uint32_t a;
    asm("{ .reg .u64 t; cvta.to.shared.u64 t, %1; cvt.u32.u64 %0, t; }" : "=r"(a) : "l"(p));
    return a;
}
#define CP16(d, s) asm volatile("cp.async.ca.shared.global [%0], [%1], 16;" :: "r"(d), "l"(s) : "memory")
#define CP_COMMIT() asm volatile("cp.async.commit_group;" ::: "memory")
#define CP_WAIT2()  asm volatile("cp.async.wait_group 2;" ::: "memory")

__device__ __forceinline__ void mma8(float c[4], uint32_t a0, uint32_t a1, uint32_t a2,
                                     uint32_t a3, uint32_t b0, uint32_t b1) {
    asm volatile(
        "mma.sync.aligned.m16n8k8.row.col.f32.tf32.tf32.f32 "
        "{%0,%1,%2,%3},{%4,%5,%6,%7},{%8,%9},{%0,%1,%2,%3};"
        : "+f"(c[0]), "+f"(c[1]), "+f"(c[2]), "+f"(c[3])
        : "r"(a0), "r"(a1), "r"(a2), "r"(a3), "r"(b0), "r"(b1));
}

// Fragment-packed index maps.
// A-pack (M=128 x K): fl = (((wm*S + s)*4 + mt)*32 + g*4 + t)*4 + slot
//   slot0=(row g, k 8s+t) slot1=(row g+8, k 8s+t) slot2=(row g, k 8s+t+4) slot3=(row g+8, k 8s+t+4)
__device__ __forceinline__ int a_idx(int S, int m, int k) {
    int wm = m >> 6, mt = (m >> 4) & 3, h = (m >> 3) & 1, g = m & 7;
    int s = k >> 3, kk = k & 7;
    return (((wm * S + s) * 4 + mt) * 32 + g * 4 + (kk & 3)) * 4 + h + 2 * (kk >> 2);
}
// B-pack (K x N): fl = ((s*NP + gp)*32 + g*4 + t)*4 + slot
//   slot0={k 8s+t, n 16gp+g} slot1={k 8s+t+4} slot2/3 = n+8 half
__device__ __forceinline__ int b_idx(int NP, int k, int n) {
    int s = k >> 3, kk = k & 7, gp = n >> 4, h = (n >> 3) & 1, g = n & 7;
    return ((s * NP + gp) * 32 + g * 4 + (kk & 3)) * 4 + 2 * h + (kk >> 2);
}

// One k8 step: A at Ap (lane-resolved, mt stride 128 fl), B at Bp (lane-resolved, l2 stride 128 fl)
template <int NT2>
__device__ __forceinline__ void mma_k8(float (&acc)[4][8][4], const float* __restrict__ Ap,
                                       const float* __restrict__ Bp) {
    float4 af[4];
#pragma unroll
    for (int mt = 0; mt < 4; mt++) af[mt] = *(const float4*)(Ap + mt * 128);
#pragma unroll
    for (int l2 = 0; l2 < NT2; l2++) {
        float4 bf = *(const float4*)(Bp + l2 * 128);
        uint32_t b0e = __float_as_uint(bf.x), b1e = __float_as_uint(bf.y);
        uint32_t b0o = __float_as_uint(bf.z), b1o = __float_as_uint(bf.w);
#pragma unroll
        for (int mt = 0; mt < 4; mt++) {
            mma8(acc[mt][2 * l2],     __float_as_uint(af[mt].x), __float_as_uint(af[mt].y),
                 __float_as_uint(af[mt].z), __float_as_uint(af[mt].w), b0e, b1e);
            mma8(acc[mt][2 * l2 + 1], __float_as_uint(af[mt].x), __float_as_uint(af[mt].y),
                 __float_as_uint(af[mt].z), __float_as_uint(af[mt].w), b0o, b1o);
        }
    }
}

// ---------------- prep 1: Wc = Wg @ Wv, bc = Wg @ bv + bg ----------------
__global__ void prep_wc(const float* __restrict__ Wg, const float* __restrict__ Wv,
                        const float* __restrict__ bv, const float* __restrict__ bg)
{
    __shared__ float sWg[CC];
    __shared__ float sred[CC];
    const int i = blockIdx.x, j = threadIdx.x;
    const float wg = Wg[i * CC + j];
    sWg[j] = wg;
    __syncthreads();
    float acc = 0.f;
#pragma unroll 8
    for (int k = 0; k < CC; ++k) acc = fmaf(sWg[k], Wv[k * CC + j], acc);
    g_Wct[i * CC + j] = acc;
    sred[j] = wg * bv[j];
    __syncthreads();
    for (int s = 128; s > 0; s >>= 1) {
        if (j < s) sred[j] += sred[j + s];
        __syncthreads();
    }
    if (j == 0) g_bc[i] = sred[0] + bg[i];
}

// ---------------- prep 2: fragment-pack weights (B = W^T, element (k,n) = W[n][k]) ----------------
__global__ void prep_pack(const float* __restrict__ Wq, const float* __restrict__ Wk)
{
    const int k = blockIdx.x, n = threadIdx.x;
    float v = (n < 128) ? Wq[n * CC + k] : Wk[(n - 128) * CC + k];
    g_WqkP[b_idx(16, k, n)] = ftf32(v);
    g_WctP[b_idx(16, k, n)] = ftf32(g_Wct[n * CC + k]);
}

// SMEM floats: scr[1024] | Buf1[32768] (xe-pack -> Q-pack|Kt-pack -> attn-pack -> ax-pack)
//            | BufB[16384] (4 x 4096 weight chunks / 2 x 8192 x-chunks)
constexpr int OFF_SCR = 0;
constexpr int OFF_A   = 1024;
constexpr int OFF_KT  = OFF_A + 16384;      // upper half of Buf1
constexpr int OFF_BB  = OFF_A + 32768;
constexpr int SMEM_FL = OFF_BB + 16384;     // 50176 fl = 200704 B
constexpr int SMEM_BYTES = SMEM_FL * 4;

__global__ void __launch_bounds__(256, 1)
fused_kernel(const float* __restrict__ x, const float* __restrict__ ee,
             const float* __restrict__ adj, const float* __restrict__ alpha_p,
             const float* __restrict__ bq, const float* __restrict__ bk,
             const float* __restrict__ gamma, const float* __restrict__ beta,
             float* __restrict__ out)
{
    extern __shared__ float sm[];
    float* scr  = sm + OFF_SCR;
    float* A1   = sm + OFF_A;    // 128KB multi-use
    float* KT   = sm + OFF_KT;   // Kt-pack then attn-pack
    float* BB   = sm + OFF_BB;
    const uint32_t bbu = smem_u32(sm + OFF_BB);

    const int tid = threadIdx.x;
    const int w = tid >> 5, lane = tid & 31;
    const int g = lane >> 2, t = lane & 3;
    const int wm = w >> 2, wn = w & 3;
    const int mrow = wm * 64;
    const int ncol = wn * 64;           // phases 1,3,4
    const int ncol2 = wn * 32;          // phase 2
    const int b = blockIdx.x;
    const float* xb = x + (size_t)b * (NF * CC);

    float acc[4][8][4];

    // Each thread copies floats [tid*16, tid*16+16): dst byte offsets d+0,16,32,48.
#define ISSUE_W(c, gW) do { \
    if ((c) < 16) { \
        uint32_t d = bbu + (((c) & 3) * 4096 + tid * 16) * 4; \
        const float* s_ = (gW) + (c) * 4096 + tid * 16; \
        CP16(d, s_); CP16(d + 16, s_ + 4); CP16(d + 32, s_ + 8); CP16(d + 48, s_ + 12); \
    } \
    CP_COMMIT(); \
} while (0)

    // prefetch first two weight chunks of phase 1
    ISSUE_W(0, g_WqkP);
    ISSUE_W(1, g_WqkP);

    // ===== stage xe = tf32(x + ee) in A-pack (S=32) =====
#pragma unroll 4
    for (int j = 0; j < 32; j++) {
        int e = j * 256 + tid;
        int r = e >> 6, k0 = (e & 63) << 2;
        float4 v = __ldg((const float4*)(xb + r * 256 + k0));
        float4 eev = __ldg((const float4*)(ee + r * 256 + k0));
        A1[a_idx(32, r, k0 + 0)] = ftf32(v.x + eev.x);
        A1[a_idx(32, r, k0 + 1)] = ftf32(v.y + eev.y);
        A1[a_idx(32, r, k0 + 2)] = ftf32(v.z + eev.z);
        A1[a_idx(32, r, k0 + 3)] = ftf32(v.w + eev.w);
    }

    // ===== Phase 1: [Q|K] = xe @ Wqk^T  (K=256, 16 chunks of 16 rows, 4-buf cp.async) =====
#pragma unroll
    for (int mt = 0; mt < 4; mt++)
#pragma unroll
        for (int nt = 0; nt < 8; nt++)
#pragma unroll
            for (int e = 0; e < 4; e++) acc[mt][nt][e] = 0.f;

    for (int c = 0; c < 16; c++) {
        ISSUE_W(c + 2, g_WqkP);
        CP_WAIT2();
        __syncthreads();
        const float* Bc = BB + (c & 3) * 4096 + wn * 512 + lane * 4;
        const float* Ac = A1 + (wm * 32 + 2 * c) * 512 + lane * 4;
        mma_k8<4>(acc, Ac, Bc);
        mma_k8<4>(acc, Ac + 512, Bc + 2048);
    }
    __syncthreads();   // all reads of xe done before overwriting Buf1

    // epilogue: Q-pack (wn<2) / Kt-pack (wn>=2), +bias, tf32
#pragma unroll
    for (int nt = 0; nt < 8; nt++) {
        const int n = ncol + nt * 8 + 2 * t;
#pragma unroll
        for (int mt = 0; mt < 4; mt++) {
            const int r0 = mrow + mt * 16 + g, r1 = r0 + 8;
            if (wn < 2) {
                float b0 = __ldg(&bq[n]), b1 = __ldg(&bq[n + 1]);
                A1[a_idx(16, r0, n)]     = ftf32(acc[mt][nt][0] + b0);
                A1[a_idx(16, r0, n + 1)] = ftf32(acc[mt][nt][1] + b1);
                A1[a_idx(16, r1, n)]     = ftf32(acc[mt][nt][2] + b0);
                A1[a_idx(16, r1, n + 1)] = ftf32(acc[mt][nt][3] + b1);
            } else {
                const int ck = n - 128;
                float b0 = __ldg(&bk[ck]), b1 = __ldg(&bk[ck + 1]);
                KT[b_idx(8, ck, r0)]     = ftf32(acc[mt][nt][0] + b0);
                KT[b_idx(8, ck + 1, r0)] = ftf32(acc[mt][nt][1] + b1);
                KT[b_idx(8, ck, r1)]     = ftf32(acc[mt][nt][2] + b0);
                KT[b_idx(8, ck + 1, r1)] = ftf32(acc[mt][nt][3] + b1);
            }
        }
    }
    __syncthreads();

    // ===== Phase 2: scores = Q @ K^T  (K=128, N=128) =====
#pragma unroll
    for (int mt = 0; mt < 4; mt++)
#pragma unroll
        for (int nt = 0; nt < 4; nt++)
#pragma unroll
            for (int e = 0; e < 4; e++) acc[mt][nt][e] = 0.f;
#pragma unroll
    for (int s = 0; s < 16; s++)
        mma_k8<2>(acc, A1 + (wm * 16 + s) * 512 + lane * 4,
                  KT + s * 1024 + wn * 256 + lane * 4);

    // ===== softmax(scores/sqrt(128) + fa*relu(adj)) -> attn-pack (overwrites Kt) =====
    {
        const float fa = __ldg(alpha_p);
        const float invs = 0.08838834764831845f;
#pragma unroll
        for (int mt = 0; mt < 4; mt++)
#pragma unroll
            for (int h = 0; h < 2; h++) {
                const int r = mrow + mt * 16 + g + h * 8;
                float mx = -3.4e38f;
#pragma unroll
                for (int nt = 0; nt < 4; nt++)
#pragma unroll
                    for (int e = 0; e < 2; e++) {
                        const int col = ncol2 + nt * 8 + 2 * t + e;
                        float v = acc[mt][nt][h * 2 + e] * invs
                                + fa * fmaxf(__ldg(&adj[r * 128 + col]), 0.f);
                        acc[mt][nt][h * 2 + e] = v;
                        mx = fmaxf(mx, v);
                    }
                mx = fmaxf(mx, __shfl_xor_sync(0xffffffffu, mx, 1));
                mx = fmaxf(mx, __shfl_xor_sync(0xffffffffu, mx, 2));
                scr[r * 4 + wn] = mx;
            }
        __syncthreads();
#pragma unroll
        for (int mt = 0; mt < 4; mt++)
#pragma unroll
            for (int h = 0; h < 2; h++) {
                const int r = mrow + mt * 16 + g + h * 8;
                const float mx = fmaxf(fmaxf(scr[r * 4], scr[r * 4 + 1]),
                                       fmaxf(scr[r * 4 + 2], scr[r * 4 + 3]));
                float s = 0.f;
#pragma unroll
                for (int nt = 0; nt < 4; nt++)
#pragma unroll
                    for (int e = 0; e < 2; e++) {
                        float p = __expf(acc[mt][nt][h * 2 + e] - mx);
                        acc[mt][nt][h * 2 + e] = p;
                        s += p;
                    }
                s += __shfl_xor_sync(0xffffffffu, s, 1);
                s += __shfl_xor_sync(0xffffffffu, s, 2);
                scr[512 + r * 4 + wn] = s;
            }
        __syncthreads();   // also guarantees all Kt reads finished before attn overwrites
#pragma unroll
        for (int mt = 0; mt < 4; mt++)
#pragma unroll
            for (int h = 0; h < 2; h++) {
                const int r = mrow + mt * 16 + g + h * 8;
                const float inv = 1.f / (scr[512 + r * 4] + scr[512 + r * 4 + 1]
                                       + scr[512 + r * 4 + 2] + scr[512 + r * 4 + 3]);
#pragma unroll
                for (int nt = 0; nt < 4; nt++)
#pragma unroll
                    for (int e = 0; e < 2; e++) {
                        const int col = ncol2 + nt * 8 + 2 * t + e;
                        KT[a_idx(16, r, col)] = ftf32(acc[mt][nt][h * 2 + e] * inv);
                    }
            }
    }
    __syncthreads();

    // ===== Phase 3: ax = attn @ x  (K=128, 4 chunks of 32 rows, 2 buffers, ldg+pack) =====
#pragma unroll
    for (int mt = 0; mt < 4; mt++)
#pragma unroll
        for (int nt = 0; nt < 8; nt++)
#pragma unroll
            for (int e = 0; e < 4; e++) acc[mt][nt][e] = 0.f;

    for (int c = 0; c < 4; c++) {
        float* buf = BB + (c & 1) * 8192;
        const float* xs = xb + c * 32 * 256;
#pragma unroll
        for (int j = 0; j < 8; j++) {
            int e = j * 256 + tid;
            int kl = e >> 6, n0 = (e & 63) << 2;
            float4 v = __ldg((const float4*)(xs + kl * 256 + n0));
            buf[b_idx(16, kl, n0 + 0)] = ftf32(v.x);
            buf[b_idx(16, kl, n0 + 1)] = ftf32(v.y);
            buf[b_idx(16, kl, n0 + 2)] = ftf32(v.z);
            buf[b_idx(16, kl, n0 + 3)] = ftf32(v.w);
        }
        __syncthreads();
#pragma unroll
        for (int sl = 0; sl < 4; sl++)
            mma_k8<4>(acc, KT + (wm * 16 + c * 4 + sl) * 512 + lane * 4,
                      buf + sl * 2048 + wn * 512 + lane * 4);
        __syncthreads();
    }

    // prefetch first two weight chunks of phase 4
    ISSUE_W(0, g_WctP);
    ISSUE_W(1, g_WctP);

    // epilogue: ax-pack (S=32) into Buf1 (Q/attn dead)
#pragma unroll
    for (int nt = 0; nt < 8; nt++) {
        const int n = ncol + nt * 8 + 2 * t;
#pragma unroll
        for (int mt = 0; mt < 4; mt++) {
            const int r0 = mrow + mt * 16 + g, r1 = r0 + 8;
            A1[a_idx(32, r0, n)]     = ftf32(acc[mt][nt][0]);
            A1[a_idx(32, r0, n + 1)] = ftf32(acc[mt][nt][1]);
            A1[a_idx(32, r1, n)]     = ftf32(acc[mt][nt][2]);
            A1[a_idx(32, r1, n + 1)] = ftf32(acc[mt][nt][3]);
        }
    }

    // ===== Phase 4: z = ax @ Wc^T  (K=256, 16 chunks, 4-buf cp.async) =====
#pragma unroll
    for (int mt = 0; mt < 4; mt++)
#pragma unroll
        for (int nt = 0; nt < 8; nt++)
#pragma unroll
            for (int e = 0; e < 4; e++) acc[mt][nt][e] = 0.f;

    for (int c = 0; c < 16; c++) {
        ISSUE_W(c + 2, g_WctP);
        CP_WAIT2();
        __syncthreads();
        const float* Bc = BB + (c & 3) * 4096 + wn * 512 + lane * 4;
        const float* Ac = A1 + (wm * 32 + 2 * c) * 512 + lane * 4;
        mma_k8<4>(acc, Ac, Bc);
        mma_k8<4>(acc, Ac + 512, Bc + 2048);
    }

    // ===== LN epilogue: h = relu(z + bc) + x; LayerNorm over C; store =====
#pragma unroll
    for (int mt = 0; mt < 4; mt++)
#pragma unroll
        for (int h = 0; h < 2; h++) {
            const int r = mrow + mt * 16 + g + h * 8;
            float s1 = 0.f, s2 = 0.f;
#pragma unroll
            for (int nt = 0; nt < 8; nt++)
#pragma unroll
                for (int e = 0; e < 2; e++) {
                    const int n = ncol + nt * 8 + 2 * t + e;
                    float hv = fmaxf(acc[mt][nt][h * 2 + e] + __ldg(&g_bc[n]), 0.f)
                             + __ldg(&xb[r * 256 + n]);
                    acc[mt][nt][h * 2 + e] = hv;
                    s1 += hv;
                    s2 += hv * hv;
                }
            s1 += __shfl_xor_sync(0xffffffffu, s1, 1);
            s1 += __shfl_xor_sync(0xffffffffu, s1, 2);
            s2 += __shfl_xor_sync(0xffffffffu, s2, 1);
            s2 += __shfl_xor_sync(0xffffffffu, s2, 2);
            scr[r * 4 + wn] = s1;
            scr[512 + r * 4 + wn] = s2;
        }
    __syncthreads();
    float* ob = out + (size_t)b * (NF * CC);
#pragma unroll
    for (int mt = 0; mt < 4; mt++)
#pragma unroll
        for (int h = 0; h < 2; h++) {
            const int r = mrow + mt * 16 + g + h * 8;
            const float S  = scr[r * 4] + scr[r * 4 + 1] + scr[r * 4 + 2] + scr[r * 4 + 3];
            const float Q2 = scr[512 + r * 4] + scr[512 + r * 4 + 1]
                           + scr[512 + r * 4 + 2] + scr[512 + r * 4 + 3];
            const float mean = S * (1.f / 256.f);
            const float rstd = rsqrtf(Q2 * (1.f / 256.f) - mean * mean + 1e-5f);
#pragma unroll
            for (int nt = 0; nt < 8; nt++) {
                const int n = ncol + nt * 8 + 2 * t;
                float2 o;
                o.x = (acc[mt][nt][h * 2 + 0] - mean) * rstd * __ldg(&gamma[n]) + __ldg(&beta[n]);
                o.y = (acc[mt][nt][h * 2 + 1] - mean) * rstd * __ldg(&gamma[n + 1]) + __ldg(&beta[n + 1]);
                *(float2*)(ob + r * 256 + n) = o;
            }
        }
#undef ISSUE_W
}

extern "C" void kernel_launch(void* const* d_in, const int* in_sizes, int n_in,
                              void* d_out, int out_size)
{
    (void)in_sizes; (void)n_in; (void)out_size;
    const float* x     = (const float*)d_in[0];
    const float* ee    = (const float*)d_in[1];
    const float* adj   = (const float*)d_in[2];
    const float* alpha = (const float*)d_in[3];
    const float* Wq    = (const float*)d_in[4];
    const float* bq    = (const float*)d_in[5];
    const float* Wk    = (const float*)d_in[6];
    const float* bk    = (const float*)d_in[7];
    const float* Wv    = (const float*)d_in[8];
    const float* bv    = (const float*)d_in[9];
    const float* Wg    = (const float*)d_in[10];
    const float* bg    = (const float*)d_in[11];
    const float* gamma = (const float*)d_in[12];
    const float* beta  = (const float*)d_in[13];
    float* out = (float*)d_out;

    cudaFuncSetAttribute(fused_kernel, cudaFuncAttributeMaxDynamicSharedMemorySize, SMEM_BYTES);
    prep_wc<<<CC, 256>>>(Wg, Wv, bv, bg);
    prep_pack<<<CC, 256>>>(Wq, Wk);
    fused_kernel<<<BT, 256, SMEM_BYTES>>>(x, ee, adj, alpha, bq, bk, gamma, beta, out);
}

// round 9
// speedup vs baseline: 3.7858x; 1.5169x over previous
#include <cuda_runtime.h>
#include <cuda_fp16.h>
#include <cstdint>

#define BT 2048
#define NF 128
#define CC 256

// Device globals (no allocations)
__device__ float    g_Wct[CC * CC];          // Wc = Wg @ Wv (fp32 temp)
__device__ uint32_t g_WqkPh[CC * CC / 2];    // fragment-packed half2 B for phase 1
__device__ uint32_t g_WctPh[CC * CC / 2];    // fragment-packed half2 B for phase 4
__device__ float    g_bc[CC];                // Wg @ bv + bg

__device__ __forceinline__ uint32_t pk(float a, float b) {
    __half2 h = __floats2half2_rn(a, b);
    return *(uint32_t*)&h;
}
__device__ __forceinline__ uint32_t smem_u32(const void* p) {
    uint32_t a;
    asm("{ .reg .u64 t; cvta.to.shared.u64 t, %1; cvt.u32.u64 %0, t; }" : "=r"(a) : "l"(p));
    return a;
}
#define CP16(d, s) asm volatile("cp.async.ca.shared.global [%0], [%1], 16;" :: "r"(d), "l"(s) : "memory")
#define CP_COMMIT() asm volatile("cp.async.commit_group;" ::: "memory")
#define CP_WAIT2()  asm volatile("cp.async.wait_group 2;" ::: "memory")

__device__ __forceinline__ void mma16(float c[4], uint4 a, uint32_t b0, uint32_t b1) {
    asm volatile(
        "mma.sync.aligned.m16n8k16.row.col.f32.f16.f16.f32 "
        "{%0,%1,%2,%3},{%4,%5,%6,%7},{%8,%9},{%0,%1,%2,%3};"
        : "+f"(c[0]), "+f"(c[1]), "+f"(c[2]), "+f"(c[3])
        : "r"(a.x), "r"(a.y), "r"(a.z), "r"(a.w), "r"(b0), "r"(b1));
}

// Fragment-packed half2 word-index maps (m16n8k16, row.col).
// A word reg r for 16x16 tile: r0=(g,2t|2t+1) r1=(g+8,..) r2=(g,2t+8|2t+9) r3=(g+8,..)
__device__ __forceinline__ int a_widx(int S, int m, int k) {
    int wm = m >> 6, mt = (m >> 4) & 3, g = m & 7, h = (m >> 3) & 1;
    int s = k >> 4, kk = k & 15, t = (kk & 7) >> 1, hi = kk >> 3;
    return (((wm * S + s) * 4 + mt) * 32 + g * 4 + t) * 4 + h + 2 * hi;
}
// B word reg: b0=(k=2t|2t+1, n=g) b1=(k=2t+8|2t+9, n=g); groups of 8 n per gp
__device__ __forceinline__ int b_widx(int NP, int k, int n) {
    int s = k >> 4, kk = k & 15, t = (kk & 7) >> 1, hi = kk >> 3;
    return ((s * NP + (n >> 3)) * 32 + (n & 7) * 4 + t) * 2 + hi;
}

// One k16 step: A lane-resolved (mt stride 128 words), B lane-resolved (nt stride 64 words)
template <int NT>
__device__ __forceinline__ void step16(float (&acc)[4][8][4], const uint32_t* __restrict__ Aw,
                                       const uint32_t* __restrict__ Bw) {
    uint4 af[4];
#pragma unroll
    for (int mt = 0; mt < 4; mt++) af[mt] = *(const uint4*)(Aw + mt * 128);
#pragma unroll
    for (int nt = 0; nt < NT; nt++) {
        uint2 bf = *(const uint2*)(Bw + nt * 64);
#pragma unroll
        for (int mt = 0; mt < 4; mt++) mma16(acc[mt][nt], af[mt], bf.x, bf.y);
    }
}

// ---------------- prep 1: Wc = Wg @ Wv, bc = Wg @ bv + bg ----------------
__global__ void prep_wc(const float* __restrict__ Wg, const float* __restrict__ Wv,
                        const float* __restrict__ bv, const float* __restrict__ bg)
{
    __shared__ float sWg[CC];
    __shared__ float sred[CC];
    const int i = blockIdx.x, j = threadIdx.x;
    const float wg = Wg[i * CC + j];
    sWg[j] = wg;
    __syncthreads();
    float acc = 0.f;
#pragma unroll 8
    for (int k = 0; k < CC; ++k) acc = fmaf(sWg[k], Wv[k * CC + j], acc);
    g_Wct[i * CC + j] = acc;
    sred[j] = wg * bv[j];
    __syncthreads();
    for (int s = 128; s > 0; s >>= 1) {
        if (j < s) sred[j] += sred[j + s];
        __syncthreads();
    }
    if (j == 0) g_bc[i] = sred[0] + bg[i];
}

// ---------------- prep 2: fragment-pack half2 weights (B(k,n) = W[n][k]) ----------------
__global__ void prep_pack(const float* __restrict__ Wq, const float* __restrict__ Wk)
{
    const int k = 2 * blockIdx.x, n = threadIdx.x;
    float q0, q1;
    if (n < 128) { q0 = Wq[n * CC + k]; q1 = Wq[n * CC + k + 1]; }
    else         { q0 = Wk[(n - 128) * CC + k]; q1 = Wk[(n - 128) * CC + k + 1]; }
    const int wi = b_widx(32, k, n);
    g_WqkPh[wi] = pk(q0, q1);
    g_WctPh[wi] = pk(g_Wct[n * CC + k], g_Wct[n * CC + k + 1]);
}

// SMEM word map: scr[1024 fl] | A1[16384] (xe-pack -> ax-pack) | Q[8192] (Q-pack -> attn-pack)
//              | Kt[8192] | BB[8192] (4 x 2048 weight chunks / 2 x 4096 x-chunks)
constexpr int OFF_SCR = 0;
constexpr int OFF_A   = 1024;
constexpr int OFF_Q   = OFF_A + 16384;
constexpr int OFF_K   = OFF_Q + 8192;
constexpr int OFF_BB  = OFF_K + 8192;
constexpr int SMEM_W  = OFF_BB + 8192;       // 41984 words
constexpr int SMEM_BYTES = SMEM_W * 4;       // 167936 B

__global__ void __launch_bounds__(256, 1)
fused_kernel(const float* __restrict__ x, const float* __restrict__ ee,
             const float* __restrict__ adj, const float* __restrict__ alpha_p,
             const float* __restrict__ bq, const float* __restrict__ bk,
             const float* __restrict__ gamma, const float* __restrict__ beta,
             float* __restrict__ out)
{
    extern __shared__ uint32_t smw[];
    float*    scr = (float*)(smw + OFF_SCR);
    uint32_t* A1  = smw + OFF_A;
    uint32_t* QW  = smw + OFF_Q;
    uint32_t* KtW = smw + OFF_K;
    uint32_t* BB  = smw + OFF_BB;
    const uint32_t bbu = smem_u32(smw + OFF_BB);

    const int tid = threadIdx.x;
    const int w = tid >> 5, lane = tid & 31;
    const int g = lane >> 2, t = lane & 3;
    const int wm = w >> 2, wn = w & 3;
    const int mrow = wm * 64;
    const int ncol = wn * 64;           // phases 1,3,4
    const int ncol2 = wn * 32;          // phase 2
    const int b = blockIdx.x;
    const float* xb = x + (size_t)b * (NF * CC);

    float acc[4][8][4];

    // chunk = 2048 words (8KB); thread copies words [tid*8, tid*8+8)
#define ISSUE_W(c, gW) do { \
    if ((c) < 16) { \
        uint32_t d = bbu + (((c) & 3) * 2048 + tid * 8) * 4; \
        const uint32_t* s_ = (gW) + (c) * 2048 + tid * 8; \
        CP16(d, s_); CP16(d + 16, s_ + 4); \
    } \
    CP_COMMIT(); \
} while (0)

    ISSUE_W(0, g_WqkPh);
    ISSUE_W(1, g_WqkPh);

    // ===== stage xe = fp16(x + ee) in A-pack (S=16) =====
#pragma unroll 4
    for (int j = 0; j < 32; j++) {
        int f = j * 256 + tid;
        int r = f >> 6, c0 = (f & 63) << 2;
        float4 v = __ldg((const float4*)(xb + r * 256 + c0));
        float4 e = __ldg((const float4*)(ee + r * 256 + c0));
        int w0 = a_widx(16, r, c0);
        A1[w0]     = pk(v.x + e.x, v.y + e.y);
        A1[w0 + 4] = pk(v.z + e.z, v.w + e.w);
    }

    // ===== Phase 1: [Q|K] = xe @ Wqk^T  (16 ksteps, 4-buf cp.async) =====
#pragma unroll
    for (int mt = 0; mt < 4; mt++)
#pragma unroll
        for (int nt = 0; nt < 8; nt++)
#pragma unroll
            for (int e = 0; e < 4; e++) acc[mt][nt][e] = 0.f;

    for (int c = 0; c < 16; c++) {
        ISSUE_W(c + 2, g_WqkPh);
        CP_WAIT2();
        __syncthreads();
        step16<8>(acc, A1 + (wm * 16 + c) * 512 + lane * 4,
                  BB + (c & 3) * 2048 + wn * 512 + lane * 2);
    }
    // epilogue: Q-pack (wn<2) / Kt-pack (wn>=2), +bias, fp16 (disjoint regions; no pre-sync)
#pragma unroll
    for (int nt = 0; nt < 8; nt++) {
        const int n = ncol + nt * 8 + 2 * t;
#pragma unroll
        for (int mt = 0; mt < 4; mt++) {
            const int r0 = mrow + mt * 16 + g, r1 = r0 + 8;
            if (wn < 2) {
                float b0 = __ldg(&bq[n]), b1 = __ldg(&bq[n + 1]);
                QW[a_widx(8, r0, n)] = pk(acc[mt][nt][0] + b0, acc[mt][nt][1] + b1);
                QW[a_widx(8, r1, n)] = pk(acc[mt][nt][2] + b0, acc[mt][nt][3] + b1);
            } else {
                const int ck = n - 128;
                float b0 = __ldg(&bk[ck]), b1 = __ldg(&bk[ck + 1]);
                KtW[b_widx(16, ck, r0)] = pk(acc[mt][nt][0] + b0, acc[mt][nt][1] + b1);
                KtW[b_widx(16, ck, r1)] = pk(acc[mt][nt][2] + b0, acc[mt][nt][3] + b1);
            }
        }
    }
    __syncthreads();

    // ===== Phase 2: scores = Q @ K^T  (8 ksteps, N=128) =====
#pragma unroll
    for (int mt = 0; mt < 4; mt++)
#pragma unroll
        for (int nt = 0; nt < 4; nt++)
#pragma unroll
            for (int e = 0; e < 4; e++) acc[mt][nt][e] = 0.f;
#pragma unroll
    for (int s = 0; s < 8; s++)
        step16<4>(acc, QW + (wm * 8 + s) * 512 + lane * 4,
                  KtW + s * 1024 + wn * 256 + lane * 2);

    // ===== softmax(scores/sqrt(128) + fa*relu(adj)) -> attn-pack (overwrites Q) =====
    {
        const float fa = __ldg(alpha_p);
        const float invs = 0.08838834764831845f;
#pragma unroll
        for (int mt = 0; mt < 4; mt++)
#pragma unroll
            for (int h = 0; h < 2; h++) {
                const int r = mrow + mt * 16 + g + h * 8;
                float mx = -3.4e38f;
#pragma unroll
                for (int nt = 0; nt < 4; nt++)
#pragma unroll
                    for (int e = 0; e < 2; e++) {
                        const int col = ncol2 + nt * 8 + 2 * t + e;
                        float v = acc[mt][nt][h * 2 + e] * invs
                                + fa * fmaxf(__ldg(&adj[r * 128 + col]), 0.f);
                        acc[mt][nt][h * 2 + e] = v;
                        mx = fmaxf(mx, v);
                    }
                mx = fmaxf(mx, __shfl_xor_sync(0xffffffffu, mx, 1));
                mx = fmaxf(mx, __shfl_xor_sync(0xffffffffu, mx, 2));
                scr[r * 4 + wn] = mx;
            }
        __syncthreads();
#pragma unroll
        for (int mt = 0; mt < 4; mt++)
#pragma unroll
            for (int h = 0; h < 2; h++) {
                const int r = mrow + mt * 16 + g + h * 8;
                const float mx = fmaxf(fmaxf(scr[r * 4], scr[r * 4 + 1]),
                                       fmaxf(scr[r * 4 + 2], scr[r * 4 + 3]));
                float s = 0.f;
#pragma unroll
                for (int nt = 0; nt < 4; nt++)
#pragma unroll
                    for (int e = 0; e < 2; e++) {
                        float p = __expf(acc[mt][nt][h * 2 + e] - mx);
                        acc[mt][nt][h * 2 + e] = p;
                        s += p;
                    }
                s += __shfl_xor_sync(0xffffffffu, s, 1);
                s += __shfl_xor_sync(0xffffffffu, s, 2);
                scr[512 + r * 4 + wn] = s;
            }
        __syncthreads();   // all Q reads complete before attn overwrites
#pragma unroll
        for (int mt = 0; mt < 4; mt++)
#pragma unroll
            for (int h = 0; h < 2; h++) {
                const int r = mrow + mt * 16 + g + h * 8;
                const float inv = 1.f / (scr[512 + r * 4] + scr[512 + r * 4 + 1]
                                       + scr[512 + r * 4 + 2] + scr[512 + r * 4 + 3]);
#pragma unroll
                for (int nt = 0; nt < 4; nt++) {
                    const int col = ncol2 + nt * 8 + 2 * t;
                    QW[a_widx(8, r, col)] = pk(acc[mt][nt][h * 2 + 0] * inv,
                                               acc[mt][nt][h * 2 + 1] * inv);
                }
            }
    }
    __syncthreads();

    // ===== Phase 3: ax = attn @ x  (4 chunks of 32 k-rows, 2 buffers) =====
#pragma unroll
    for (int mt = 0; mt < 4; mt++)
#pragma unroll
        for (int nt = 0; nt < 8; nt++)
#pragma unroll
            for (int e = 0; e < 4; e++) acc[mt][nt][e] = 0.f;

    for (int c = 0; c < 4; c++) {
        uint32_t* buf = BB + (c & 1) * 4096;
        const float* xs = xb + c * 32 * 256;
#pragma unroll
        for (int j = 0; j < 4; j++) {
            int idx = j * 256 + tid;
            int rp = idx >> 6, c4 = (idx & 63) << 2;
            float4 va = __ldg((const float4*)(xs + (2 * rp) * 256 + c4));
            float4 vb = __ldg((const float4*)(xs + (2 * rp + 1) * 256 + c4));
            const int sl = rp >> 3, tt = rp & 3, hi = (rp >> 2) & 1;
            const float ax[4] = {va.x, va.y, va.z, va.w};
            const float bx[4] = {vb.x, vb.y, vb.z, vb.w};
#pragma unroll
            for (int i = 0; i < 4; i++) {
                int n = c4 + i;
                buf[((sl * 32 + (n >> 3)) * 32 + (n & 7) * 4 + tt) * 2 + hi] = pk(ax[i], bx[i]);
            }
        }
        __syncthreads();
#pragma unroll
        for (int sl = 0; sl < 2; sl++)
            step16<8>(acc, QW + (wm * 8 + c * 2 + sl) * 512 + lane * 4,
                      buf + sl * 2048 + wn * 512 + lane * 2);
        __syncthreads();
    }

    // prefetch first two weight chunks of phase 4
    ISSUE_W(0, g_WctPh);
    ISSUE_W(1, g_WctPh);

    // epilogue: ax-pack (S=16) into A1 (xe dead)
#pragma unroll
    for (int nt = 0; nt < 8; nt++) {
        const int n = ncol + nt * 8 + 2 * t;
#pragma unroll
        for (int mt = 0; mt < 4; mt++) {
            const int r0 = mrow + mt * 16 + g, r1 = r0 + 8;
            A1[a_widx(16, r0, n)] = pk(acc[mt][nt][0], acc[mt][nt][1]);
            A1[a_widx(16, r1, n)] = pk(acc[mt][nt][2], acc[mt][nt][3]);
        }
    }

    // ===== Phase 4: z = ax @ Wc^T  (16 ksteps, 4-buf cp.async) =====
#pragma unroll
    for (int mt = 0; mt < 4; mt++)
#pragma unroll
        for (int nt = 0; nt < 8; nt++)
#pragma unroll
            for (int e = 0; e < 4; e++) acc[mt][nt][e] = 0.f;

    for (int c = 0; c < 16; c++) {
        ISSUE_W(c + 2, g_WctPh);
        CP_WAIT2();
        __syncthreads();
        step16<8>(acc, A1 + (wm * 16 + c) * 512 + lane * 4,
                  BB + (c & 3) * 2048 + wn * 512 + lane * 2);
    }

    // ===== LN epilogue: h = relu(z + bc) + x; LayerNorm over C; store =====
#pragma unroll
    for (int mt = 0; mt < 4; mt++)
#pragma unroll
        for (int h = 0; h < 2; h++) {
            const int r = mrow + mt * 16 + g + h * 8;
            float s1 = 0.f, s2 = 0.f;
#pragma unroll
            for (int nt = 0; nt < 8; nt++)
#pragma unroll
                for (int e = 0; e < 2; e++) {
                    const int n = ncol + nt * 8 + 2 * t + e;
                    float hv = fmaxf(acc[mt][nt][h * 2 + e] + __ldg(&g_bc[n]), 0.f)
                             + __ldg(&xb[r * 256 + n]);
                    acc[mt][nt][h * 2 + e] = hv;
                    s1 += hv;
                    s2 += hv * hv;
                }
            s1 += __shfl_xor_sync(0xffffffffu, s1, 1);
            s1 += __shfl_xor_sync(0xffffffffu, s1, 2);
            s2 += __shfl_xor_sync(0xffffffffu, s2, 1);
            s2 += __shfl_xor_sync(0xffffffffu, s2, 2);
            scr[r * 4 + wn] = s1;
            scr[512 + r * 4 + wn] = s2;
        }
    __syncthreads();
    float* ob = out + (size_t)b * (NF * CC);
#pragma unroll
    for (int mt = 0; mt < 4; mt++)
#pragma unroll
        for (int h = 0; h < 2; h++) {
            const int r = mrow + mt * 16 + g + h * 8;
            const float S  = scr[r * 4] + scr[r * 4 + 1] + scr[r * 4 + 2] + scr[r * 4 + 3];
            const float Q2 = scr[512 + r * 4] + scr[512 + r * 4 + 1]
                           + scr[512 + r * 4 + 2] + scr[512 + r * 4 + 3];
            const float mean = S * (1.f / 256.f);
            const float rstd = rsqrtf(Q2 * (1.f / 256.f) - mean * mean + 1e-5f);
#pragma unroll
            for (int nt = 0; nt < 8; nt++) {
                const int n = ncol + nt * 8 + 2 * t;
                float2 o;
                o.x = (acc[mt][nt][h * 2 + 0] - mean) * rstd * __ldg(&gamma[n]) + __ldg(&beta[n]);
                o.y = (acc[mt][nt][h * 2 + 1] - mean) * rstd * __ldg(&gamma[n + 1]) + __ldg(&beta[n + 1]);
                *(float2*)(ob + r * 256 + n) = o;
            }
        }
#undef ISSUE_W
}

extern "C" void kernel_launch(void* const* d_in, const int* in_sizes, int n_in,
                              void* d_out, int out_size)
{
    (void)in_sizes; (void)n_in; (void)out_size;
    const float* x     = (const float*)d_in[0];
    const float* ee    = (const float*)d_in[1];
    const float* adj   = (const float*)d_in[2];
    const float* alpha = (const float*)d_in[3];
    const float* Wq    = (const float*)d_in[4];
    const float* bq    = (const float*)d_in[5];
    const float* Wk    = (const float*)d_in[6];
    const float* bk    = (const float*)d_in[7];
    const float* Wv    = (const float*)d_in[8];
    const float* bv    = (const float*)d_in[9];
    const float* Wg    = (const float*)d_in[10];
    const float* bg    = (const float*)d_in[11];
    const float* gamma = (const float*)d_in[12];
    const float* beta  = (const float*)d_in[13];
    float* out = (float*)d_out;

    cudaFuncSetAttribute(fused_kernel, cudaFuncAttributeMaxDynamicSharedMemorySize, SMEM_BYTES);
    prep_wc<<<CC, 256>>>(Wg, Wv, bv, bg);
    prep_pack<<<128, 256>>>(Wq, Wk);
    fused_kernel<<<BT, 256, SMEM_BYTES>>>(x, ee, adj, alpha, bq, bk, gamma, beta, out);
}

// round 10
// speedup vs baseline: 4.2159x; 1.1136x over previous
#include <cuda_runtime.h>
#include <cuda_fp16.h>
#include <cstdint>

#define BT 2048
#define NF 128
#define CC 256

// Device globals (no allocations)
__device__ float    g_Wct[CC * CC];          // Wc = Wg @ Wv (fp32 temp)
__device__ uint32_t g_WqkPh[CC * CC / 2];    // fragment-packed half2 B for phase 1
__device__ uint32_t g_WctPh[CC * CC / 2];    // fragment-packed half2 B for phase 4
__device__ float    g_bc[CC];                // Wg @ bv + bg

__device__ __forceinline__ uint32_t pk(float a, float b) {
    __half2 h = __floats2half2_rn(a, b);
    return *(uint32_t*)&h;
}
__device__ __forceinline__ uint32_t smem_u32(const void* p) {
    uint32_t a;
    asm("{ .reg .u64 t; cvta.to.shared.u64 t, %1; cvt.u32.u64 %0, t; }" : "=r"(a) : "l"(p));
    return a;
}
#define CP16(d, s) asm volatile("cp.async.ca.shared.global [%0], [%1], 16;" :: "r"(d), "l"(s) : "memory")
#define CP_COMMIT() asm volatile("cp.async.commit_group;" ::: "memory")
#define CP_WAIT2()  asm volatile("cp.async.wait_group 2;" ::: "memory")

__device__ __forceinline__ void mma16(float c[4], uint4 a, uint32_t b0, uint32_t b1) {
    asm volatile(
        "mma.sync.aligned.m16n8k16.row.col.f32.f16.f16.f32 "
        "{%0,%1,%2,%3},{%4,%5,%6,%7},{%8,%9},{%0,%1,%2,%3};"
        : "+f"(c[0]), "+f"(c[1]), "+f"(c[2]), "+f"(c[3])
        : "r"(a.x), "r"(a.y), "r"(a.z), "r"(a.w), "r"(b0), "r"(b1));
}

// A-pack word index, 32-row slabs (m16n8k16 row fragment order).
//   fl = (((slab*S + s)*2 + mt)*32 + g*4 + t)*4 + h + 2*hi
__device__ __forceinline__ int a_w(int S, int m, int k) {
    int slab = m >> 5, mt = (m >> 4) & 1, h = (m >> 3) & 1, g = m & 7;
    int s = k >> 4, kk = k & 15, t = (kk & 7) >> 1, hi = kk >> 3;
    return (((slab * S + s) * 2 + mt) * 32 + g * 4 + t) * 4 + h + 2 * hi;
}
// B-pack word index: b0=(k=2t|2t+1, n) b1=(k+8 pair); 8-n groups
__device__ __forceinline__ int b_w(int NP, int k, int n) {
    int s = k >> 4, kk = k & 15, t = (kk & 7) >> 1, hi = kk >> 3;
    return ((s * NP + (n >> 3)) * 32 + (n & 7) * 4 + t) * 2 + hi;
}

// One k16 step: warp tile 32 x (NT*8). A mt stride 128 words, B nt stride 64 words.
template <int NT>
__device__ __forceinline__ void step16(float (&acc)[2][8][4], const uint32_t* __restrict__ Aw,
                                       const uint32_t* __restrict__ Bw) {
    uint4 af[2];
#pragma unroll
    for (int mt = 0; mt < 2; mt++) af[mt] = *(const uint4*)(Aw + mt * 128);
#pragma unroll
    for (int nt = 0; nt < NT; nt++) {
        uint2 bf = *(const uint2*)(Bw + nt * 64);
#pragma unroll
        for (int mt = 0; mt < 2; mt++) mma16(acc[mt][nt], af[mt], bf.x, bf.y);
    }
}

// ---------------- prep 1: Wc = Wg @ Wv, bc = Wg @ bv + bg ----------------
__global__ void prep_wc(const float* __restrict__ Wg, const float* __restrict__ Wv,
                        const float* __restrict__ bv, const float* __restrict__ bg)
{
    __shared__ float sWg[CC];
    __shared__ float sred[CC];
    const int i = blockIdx.x, j = threadIdx.x;
    const float wg = Wg[i * CC + j];
    sWg[j] = wg;
    __syncthreads();
    float acc = 0.f;
#pragma unroll 8
    for (int k = 0; k < CC; ++k) acc = fmaf(sWg[k], Wv[k * CC + j], acc);
    g_Wct[i * CC + j] = acc;
    sred[j] = wg * bv[j];
    __syncthreads();
    for (int s = 128; s > 0; s >>= 1) {
        if (j < s) sred[j] += sred[j + s];
        __syncthreads();
    }
    if (j == 0) g_bc[i] = sred[0] + bg[i];
}

// ---------------- prep 2: fragment-pack half2 weights (B(k,n) = W[n][k]) ----------------
__global__ void prep_pack(const float* __restrict__ Wq, const float* __restrict__ Wk)
{
    const int k = 2 * blockIdx.x, n = threadIdx.x;
    float q0, q1;
    if (n < 128) { q0 = Wq[n * CC + k]; q1 = Wq[n * CC + k + 1]; }
    else         { q0 = Wk[(n - 128) * CC + k]; q1 = Wk[(n - 128) * CC + k + 1]; }
    const int wi = b_w(32, k, n);
    g_WqkPh[wi] = pk(q0, q1);
    g_WctPh[wi] = pk(g_Wct[n * CC + k], g_Wct[n * CC + k + 1]);
}

// SMEM word map: scr[1024] | A1[16384] (xe -> Q|Kt -> attn|Kt -> ax) | BB[8192]
//   Q region = A1[0..8192) (S=8 pack), Kt region = A1[8192..16384)
constexpr int OFF_SCR = 0;
constexpr int OFF_A   = 1024;
constexpr int OFF_K   = OFF_A + 8192;
constexpr int OFF_BB  = OFF_A + 16384;
constexpr int SMEM_W  = OFF_BB + 8192;       // 25600 words
constexpr int SMEM_BYTES = SMEM_W * 4;       // 102400 B

__global__ void __launch_bounds__(512, 1)
fused_kernel(const float* __restrict__ x, const float* __restrict__ ee,
             const float* __restrict__ adj, const float* __restrict__ alpha_p,
             const float* __restrict__ bq, const float* __restrict__ bk,
             const float* __restrict__ gamma, const float* __restrict__ beta,
             float* __restrict__ out)
{
    extern __shared__ uint32_t smw[];
    float*    scr = (float*)(smw + OFF_SCR);
    uint32_t* A1  = smw + OFF_A;     // xe-pack (S=16) / ax-pack (S=16)
    uint32_t* QW  = smw + OFF_A;     // Q-pack (S=8) then attn-pack
    uint32_t* KtW = smw + OFF_K;     // Kt-pack (NP=16)
    uint32_t* BB  = smw + OFF_BB;
    const uint32_t bbu = smem_u32(smw + OFF_BB);

    const int tid = threadIdx.x;
    const int w = tid >> 5, lane = tid & 31;
    const int g = lane >> 2, t = lane & 3;
    const int wm = w >> 2, wn = w & 3;          // 4 x 4 warp grid
    const int mrow = wm * 32;
    const int ncol = wn * 64;                   // phases 1,3,4 (N=256)
    const int ncol2 = wn * 32;                  // phase 2 (N=128)
    const int b = blockIdx.x;
    const float* xb = x + (size_t)b * (NF * CC);

    float acc[2][8][4];

    // weight chunk = 2048 words (8KB); each of 512 threads copies 4 words (16B)
#define ISSUE_W(c, gW) do { \
    if ((c) < 16) { \
        uint32_t d = bbu + (((c) & 3) * 2048 + tid * 4) * 4; \
        CP16(d, (gW) + (c) * 2048 + tid * 4); \
    } \
    CP_COMMIT(); \
} while (0)

    ISSUE_W(0, g_WqkPh);
    ISSUE_W(1, g_WqkPh);

    // ===== stage xe = fp16(x + ee) in A-pack (S=16) =====
#pragma unroll 4
    for (int j = 0; j < 16; j++) {
        int f = j * 512 + tid;
        int r = f >> 6, c0 = (f & 63) << 2;
        float4 v = __ldg((const float4*)(xb + r * 256 + c0));
        float4 e = __ldg((const float4*)(ee + r * 256 + c0));
        int w0 = a_w(16, r, c0);
        A1[w0]     = pk(v.x + e.x, v.y + e.y);
        A1[w0 + 4] = pk(v.z + e.z, v.w + e.w);
    }

    // ===== Phase 1: [Q|K] = xe @ Wqk^T  (16 ksteps, 4-buf cp.async) =====
#pragma unroll
    for (int mt = 0; mt < 2; mt++)
#pragma unroll
        for (int nt = 0; nt < 8; nt++)
#pragma unroll
            for (int e = 0; e < 4; e++) acc[mt][nt][e] = 0.f;

    for (int c = 0; c < 16; c++) {
        ISSUE_W(c + 2, g_WqkPh);
        CP_WAIT2();
        __syncthreads();
        step16<8>(acc, A1 + wm * 4096 + c * 256 + lane * 4,
                  BB + (c & 3) * 2048 + wn * 512 + lane * 2);
    }
    __syncthreads();   // all xe reads done before Q/Kt overwrite A1

    // epilogue: Q-pack (wn<2, S=8) / Kt-pack (wn>=2, NP=16), +bias, fp16
#pragma unroll
    for (int nt = 0; nt < 8; nt++) {
        const int n = ncol + nt * 8 + 2 * t;
#pragma unroll
        for (int mt = 0; mt < 2; mt++) {
            const int r0 = mrow + mt * 16 + g, r1 = r0 + 8;
            if (wn < 2) {
                float b0 = __ldg(&bq[n]), b1 = __ldg(&bq[n + 1]);
                QW[a_w(8, r0, n)] = pk(acc[mt][nt][0] + b0, acc[mt][nt][1] + b1);
                QW[a_w(8, r1, n)] = pk(acc[mt][nt][2] + b0, acc[mt][nt][3] + b1);
            } else {
                const int ck = n - 128;
                float b0 = __ldg(&bk[ck]), b1 = __ldg(&bk[ck + 1]);
                KtW[b_w(16, ck, r0)] = pk(acc[mt][nt][0] + b0, acc[mt][nt][1] + b1);
                KtW[b_w(16, ck, r1)] = pk(acc[mt][nt][2] + b0, acc[mt][nt][3] + b1);
            }
        }
    }
    __syncthreads();

    // ===== Phase 2: scores = Q @ K^T  (8 ksteps, N=128; warp tile 32x32) =====
#pragma unroll
    for (int mt = 0; mt < 2; mt++)
#pragma unroll
        for (int nt = 0; nt < 4; nt++)
#pragma unroll
            for (int e = 0; e < 4; e++) acc[mt][nt][e] = 0.f;
#pragma unroll
    for (int s = 0; s < 8; s++)
        step16<4>(acc, QW + wm * 2048 + s * 256 + lane * 4,
                  KtW + s * 1024 + wn * 256 + lane * 2);

    // ===== softmax(scores/sqrt(128) + fa*relu(adj)) -> attn-pack (overwrites Q) =====
    {
        const float fa = __ldg(alpha_p);
        const float invs = 0.08838834764831845f;
#pragma unroll
        for (int mt = 0; mt < 2; mt++)
#pragma unroll
            for (int h = 0; h < 2; h++) {
                const int r = mrow + mt * 16 + g + h * 8;
                float mx = -3.4e38f;
#pragma unroll
                for (int nt = 0; nt < 4; nt++)
#pragma unroll
                    for (int e = 0; e < 2; e++) {
                        const int col = ncol2 + nt * 8 + 2 * t + e;
                        float v = acc[mt][nt][h * 2 + e] * invs
                                + fa * fmaxf(__ldg(&adj[r * 128 + col]), 0.f);
                        acc[mt][nt][h * 2 + e] = v;
                        mx = fmaxf(mx, v);
                    }
                mx = fmaxf(mx, __shfl_xor_sync(0xffffffffu, mx, 1));
                mx = fmaxf(mx, __shfl_xor_sync(0xffffffffu, mx, 2));
                scr[r * 4 + wn] = mx;
            }
        __syncthreads();
#pragma unroll
        for (int mt = 0; mt < 2; mt++)
#pragma unroll
            for (int h = 0; h < 2; h++) {
                const int r = mrow + mt * 16 + g + h * 8;
                const float mx = fmaxf(fmaxf(scr[r * 4], scr[r * 4 + 1]),
                                       fmaxf(scr[r * 4 + 2], scr[r * 4 + 3]));
                float s = 0.f;
#pragma unroll
                for (int nt = 0; nt < 4; nt++)
#pragma unroll
                    for (int e = 0; e < 2; e++) {
                        float p = __expf(acc[mt][nt][h * 2 + e] - mx);
                        acc[mt][nt][h * 2 + e] = p;
                        s += p;
                    }
                s += __shfl_xor_sync(0xffffffffu, s, 1);
                s += __shfl_xor_sync(0xffffffffu, s, 2);
                scr[512 + r * 4 + wn] = s;
            }
        __syncthreads();   // all Q reads complete before attn overwrites
#pragma unroll
        for (int mt = 0; mt < 2; mt++)
#pragma unroll
            for (int h = 0; h < 2; h++) {
                const int r = mrow + mt * 16 + g + h * 8;
                const float inv = 1.f / (scr[512 + r * 4] + scr[512 + r * 4 + 1]
                                       + scr[512 + r * 4 + 2] + scr[512 + r * 4 + 3]);
#pragma unroll
                for (int nt = 0; nt < 4; nt++) {
                    const int col = ncol2 + nt * 8 + 2 * t;
                    QW[a_w(8, r, col)] = pk(acc[mt][nt][h * 2 + 0] * inv,
                                            acc[mt][nt][h * 2 + 1] * inv);
                }
            }
    }
    __syncthreads();

    // ===== Phase 3: ax = attn @ x  (4 chunks of 32 k-rows, 2 x 16KB buffers) =====
#pragma unroll
    for (int mt = 0; mt < 2; mt++)
#pragma unroll
        for (int nt = 0; nt < 8; nt++)
#pragma unroll
            for (int e = 0; e < 4; e++) acc[mt][nt][e] = 0.f;

    for (int c = 0; c < 4; c++) {
        uint32_t* buf = BB + (c & 1) * 4096;
        const float* xs = xb + c * 32 * 256;
#pragma unroll
        for (int j = 0; j < 2; j++) {
            int idx = j * 512 + tid;
            int rp = idx >> 6, c4 = (idx & 63) << 2;     // row-pair 0..15, col group
            float4 va = __ldg((const float4*)(xs + (2 * rp) * 256 + c4));
            float4 vb = __ldg((const float4*)(xs + (2 * rp + 1) * 256 + c4));
            const int sl = rp >> 3, tt = rp & 3, hi = (rp >> 2) & 1;
            const float ax[4] = {va.x, va.y, va.z, va.w};
            const float bx[4] = {vb.x, vb.y, vb.z, vb.w};
#pragma unroll
            for (int i = 0; i < 4; i++) {
                int n = c4 + i;
                buf[((sl * 32 + (n >> 3)) * 32 + (n & 7) * 4 + tt) * 2 + hi] = pk(ax[i], bx[i]);
            }
        }
        __syncthreads();
#pragma unroll
        for (int sl = 0; sl < 2; sl++)
            step16<8>(acc, QW + wm * 2048 + (c * 2 + sl) * 256 + lane * 4,
                      buf + sl * 2048 + wn * 512 + lane * 2);
        __syncthreads();
    }

    // prefetch first two weight chunks of phase 4
    ISSUE_W(0, g_WctPh);
    ISSUE_W(1, g_WctPh);

    // epilogue: ax-pack (S=16) into A1 (attn/Kt dead)
#pragma unroll
    for (int nt = 0; nt < 8; nt++) {
        const int n = ncol + nt * 8 + 2 * t;
#pragma unroll
        for (int mt = 0; mt < 2; mt++) {
            const int r0 = mrow + mt * 16 + g, r1 = r0 + 8;
            A1[a_w(16, r0, n)] = pk(acc[mt][nt][0], acc[mt][nt][1]);
            A1[a_w(16, r1, n)] = pk(acc[mt][nt][2], acc[mt][nt][3]);
        }
    }

    // ===== Phase 4: z = ax @ Wc^T  (16 ksteps, 4-buf cp.async) =====
#pragma unroll
    for (int mt = 0; mt < 2; mt++)
#pragma unroll
        for (int nt = 0; nt < 8; nt++)
#pragma unroll
            for (int e = 0; e < 4; e++) acc[mt][nt][e] = 0.f;

    for (int c = 0; c < 16; c++) {
        ISSUE_W(c + 2, g_WctPh);
        CP_WAIT2();
        __syncthreads();
        step16<8>(acc, A1 + wm * 4096 + c * 256 + lane * 4,
                  BB + (c & 3) * 2048 + wn * 512 + lane * 2);
    }

    // ===== LN epilogue: h = relu(z + bc) + x; LayerNorm over C; store =====
#pragma unroll
    for (int mt = 0; mt < 2; mt++)
#pragma unroll
        for (int h = 0; h < 2; h++) {
            const int r = mrow + mt * 16 + g + h * 8;
            float s1 = 0.f, s2 = 0.f;
#pragma unroll
            for (int nt = 0; nt < 8; nt++)
#pragma unroll
                for (int e = 0; e < 2; e++) {
                    const int n = ncol + nt * 8 + 2 * t + e;
                    float hv = fmaxf(acc[mt][nt][h * 2 + e] + __ldg(&g_bc[n]), 0.f)
                             + __ldg(&xb[r * 256 + n]);
                    acc[mt][nt][h * 2 + e] = hv;
                    s1 += hv;
                    s2 += hv * hv;
                }
            s1 += __shfl_xor_sync(0xffffffffu, s1, 1);
            s1 += __shfl_xor_sync(0xffffffffu, s1, 2);
            s2 += __shfl_xor_sync(0xffffffffu, s2, 1);
            s2 += __shfl_xor_sync(0xffffffffu, s2, 2);
            scr[r * 4 + wn] = s1;
            scr[512 + r * 4 + wn] = s2;
        }
    __syncthreads();
    float* ob = out + (size_t)b * (NF * CC);
#pragma unroll
    for (int mt = 0; mt < 2; mt++)
#pragma unroll
        for (int h = 0; h < 2; h++) {
            const int r = mrow + mt * 16 + g + h * 8;
            const float S  = scr[r * 4] + scr[r * 4 + 1] + scr[r * 4 + 2] + scr[r * 4 + 3];
            const float Q2 = scr[512 + r * 4] + scr[512 + r * 4 + 1]
                           + scr[512 + r * 4 + 2] + scr[512 + r * 4 + 3];
            const float mean = S * (1.f / 256.f);
            const float rstd = rsqrtf(Q2 * (1.f / 256.f) - mean * mean + 1e-5f);
#pragma unroll
            for (int nt = 0; nt < 8; nt++) {
                const int n = ncol + nt * 8 + 2 * t;
                float2 o;
                o.x = (acc[mt][nt][h * 2 + 0] - mean) * rstd * __ldg(&gamma[n]) + __ldg(&beta[n]);
                o.y = (acc[mt][nt][h * 2 + 1] - mean) * rstd * __ldg(&gamma[n + 1]) + __ldg(&beta[n + 1]);
                *(float2*)(ob + r * 256 + n) = o;
            }
        }
#undef ISSUE_W
}

extern "C" void kernel_launch(void* const* d_in, const int* in_sizes, int n_in,
                              void* d_out, int out_size)
{
    (void)in_sizes; (void)n_in; (void)out_size;
    const float* x     = (const float*)d_in[0];
    const float* ee    = (const float*)d_in[1];
    const float* adj   = (const float*)d_in[2];
    const float* alpha = (const float*)d_in[3];
    const float* Wq    = (const float*)d_in[4];
    const float* bq    = (const float*)d_in[5];
    const float* Wk    = (const float*)d_in[6];
    const float* bk    = (const float*)d_in[7];
    const float* Wv    = (const float*)d_in[8];
    const float* bv    = (const float*)d_in[9];
    const float* Wg    = (const float*)d_in[10];
    const float* bg    = (const float*)d_in[11];
    const float* gamma = (const float*)d_in[12];
    const float* beta  = (const float*)d_in[13];
    float* out = (float*)d_out;

    cudaFuncSetAttribute(fused_kernel, cudaFuncAttributeMaxDynamicSharedMemorySize, SMEM_BYTES);
    prep_wc<<<CC, 256>>>(Wg, Wv, bv, bg);
    prep_pack<<<128, 256>>>(Wq, Wk);
    fused_kernel<<<BT, 512, SMEM_BYTES>>>(x, ee, adj, alpha, bq, bk, gamma, beta, out);
}